// round 2
// baseline (speedup 1.0000x reference)
#include <cuda_runtime.h>
#include <math.h>
#include <stdint.h>

#define NS 1024
#define NQ 8192
#define DD 256
#define EPSR 0.05f
#define INV_EPS 20.0f
#define THRESHV 1e-3f
#define MAX_ITER 100
#define SPLITK 8

// log(1/Ns + 1e-8), log(1/Nq + 1e-8) computed in double precision offline
#define LOG_MU  (-6.93146156565f)
#define LOG_NU  (-9.01083143063f)

// ---------------- device scratch (static, no allocations) ----------------
__device__ float g_C[(size_t)NS * NQ];          // cost matrix, later overwritten with weights
__device__ float g_u[NS];
__device__ float g_v[NQ];
__device__ float g_rowerr[NS];
__device__ float g_m[NS];
__device__ float g_sinv[NS];
__device__ float g_x2[NS];
__device__ float g_y2[NQ];
__device__ float g_part[(size_t)SPLITK * NS * DD];
__device__ int   g_done;

// ---------------- fast exp: FMA-only (no MUFU), ~1e-7 rel err ----------------
__device__ __forceinline__ float fexp(float x) {
    x = fmaxf(x, -87.0f);                      // exp(-87) ~ 1.6e-38; avoids bad scalb
    float t = x * 1.4426950408889634f;         // x * log2(e)
    float n = rintf(t);
    float f = t - n;                            // f in [-0.5, 0.5]
    // 2^f = sum (ln2*f)^k/k!, degree 6
    float p = 1.540353039e-4f;
    p = fmaf(p, f, 1.333355815e-3f);
    p = fmaf(p, f, 9.618129108e-3f);
    p = fmaf(p, f, 5.550410866e-2f);
    p = fmaf(p, f, 2.402265070e-1f);
    p = fmaf(p, f, 6.931471806e-1f);
    p = fmaf(p, f, 1.0f);
    int e = (int)n;
    return p * __int_as_float((e + 127) << 23);
}

// ---------------- init (runs at start of every graph replay) ----------------
__global__ void k_init() {
    int t = blockIdx.x * blockDim.x + threadIdx.x;
    if (t < NS) g_u[t] = 0.0f;
    if (t < NQ) g_v[t] = 0.0f;
    if (t == 0) g_done = 0;
}

// ---------------- squared norms: one warp per row ----------------
__global__ void k_norms(const float* __restrict__ zs, const float* __restrict__ zq) {
    int warp = (blockIdx.x * blockDim.x + threadIdx.x) >> 5;
    int lane = threadIdx.x & 31;
    if (warp >= NS + NQ) return;
    const float* row;
    float* out;
    if (warp < NS) { row = zs + (size_t)warp * DD;        out = g_x2 + warp; }
    else           { row = zq + (size_t)(warp - NS) * DD; out = g_y2 + (warp - NS); }
    float s = 0.0f;
    #pragma unroll
    for (int k = lane; k < DD; k += 32) { float v = row[k]; s = fmaf(v, v, s); }
    #pragma unroll
    for (int off = 16; off; off >>= 1) s += __shfl_down_sync(0xffffffffu, s, off);
    if (lane == 0) *out = s;
}

// ---------------- cost matrix: C = x2 + y2 - 2*A@B^T (fp32, 128x128 tile) ----------------
__global__ __launch_bounds__(256) void k_cost(const float* __restrict__ A,
                                              const float* __restrict__ B) {
    __shared__ float As[16][128];
    __shared__ float Bs[16][128];
    int tx = threadIdx.x & 15, ty = threadIdx.x >> 4;
    int m0 = blockIdx.y * 128;
    int n0 = blockIdx.x * 128;
    float acc[8][8] = {};
    for (int k0 = 0; k0 < DD; k0 += 16) {
        #pragma unroll
        for (int t = 0; t < 2; t++) {
            int f  = threadIdx.x + t * 256;
            int r  = f >> 2, k4 = f & 3;
            float4 va = *reinterpret_cast<const float4*>(A + (size_t)(m0 + r) * DD + k0 + k4 * 4);
            As[k4*4+0][r] = va.x; As[k4*4+1][r] = va.y; As[k4*4+2][r] = va.z; As[k4*4+3][r] = va.w;
            float4 vb = *reinterpret_cast<const float4*>(B + (size_t)(n0 + r) * DD + k0 + k4 * 4);
            Bs[k4*4+0][r] = vb.x; Bs[k4*4+1][r] = vb.y; Bs[k4*4+2][r] = vb.z; Bs[k4*4+3][r] = vb.w;
        }
        __syncthreads();
        #pragma unroll
        for (int kk = 0; kk < 16; kk++) {
            float a[8], b[8];
            #pragma unroll
            for (int q = 0; q < 8; q++) { a[q] = As[kk][ty*8+q]; b[q] = Bs[kk][tx*8+q]; }
            #pragma unroll
            for (int ii = 0; ii < 8; ii++)
                #pragma unroll
                for (int jj = 0; jj < 8; jj++)
                    acc[ii][jj] = fmaf(a[ii], b[jj], acc[ii][jj]);
        }
        __syncthreads();
    }
    #pragma unroll
    for (int ii = 0; ii < 8; ii++) {
        int i = m0 + ty * 8 + ii;
        float x2 = g_x2[i];
        float* crow = g_C + (size_t)i * NQ + n0 + tx * 8;
        #pragma unroll
        for (int jj = 0; jj < 8; jj++) {
            int j = n0 + tx * 8 + jj;
            crow[jj] = x2 + g_y2[j] - 2.0f * acc[ii][jj];
        }
    }
}

// ---------------- online LSE combine helpers ----------------
__device__ __forceinline__ void lse_combine(float& m, float& s, float m2, float s2) {
    float mn = fmaxf(m, m2);
    s = s * fexp(m - mn) + s2 * fexp(m2 - mn);
    m = mn;
}

// block-reduce (m,s) across 256 threads; result valid on thread 0
__device__ __forceinline__ void lse_block_reduce(float& m, float& s) {
    int lane = threadIdx.x & 31;
    int wid  = threadIdx.x >> 5;
    #pragma unroll
    for (int off = 16; off; off >>= 1) {
        float m2 = __shfl_down_sync(0xffffffffu, m, off);
        float s2 = __shfl_down_sync(0xffffffffu, s, off);
        lse_combine(m, s, m2, s2);
    }
    __shared__ float smm[8], sms[8];
    if (lane == 0) { smm[wid] = m; sms[wid] = s; }
    __syncthreads();
    if (threadIdx.x == 0) {
        m = smm[0]; s = sms[0];
        #pragma unroll
        for (int w = 1; w < 8; w++) lse_combine(m, s, smm[w], sms[w]);
    }
}

// ---------------- u update: row LSE over NQ ----------------
__global__ __launch_bounds__(256) void k_update_u() {
    if (g_done) return;
    int i = blockIdx.x;
    const float* Crow = g_C + (size_t)i * NQ;
    float m = -1e30f, s = 0.0f;
    #pragma unroll 4
    for (int j = threadIdx.x; j < NQ; j += 256) {
        float a  = (g_v[j] - Crow[j]) * INV_EPS;
        float mn = fmaxf(m, a);
        s = fmaf(s, fexp(m - mn), fexp(a - mn));
        m = mn;
    }
    lse_block_reduce(m, s);
    if (threadIdx.x == 0) {
        float L    = m + logf(s);
        float unew = EPSR * (LOG_MU - L);
        g_rowerr[i] = fabsf(unew - g_u[i]);
        g_u[i] = unew;
    }
}

// ---------------- v update: column LSE over NS ----------------
__global__ __launch_bounds__(256) void k_update_v() {
    if (g_done) return;
    int c = threadIdx.x & 31;       // column within block group
    int p = threadIdx.x >> 5;       // row partition 0..7 (128 rows each)
    int j = blockIdx.x * 32 + c;
    float m = -1e30f, s = 0.0f;
    int i0 = p * 128;
    #pragma unroll 4
    for (int ii = 0; ii < 128; ii++) {
        int i = i0 + ii;
        float a  = (g_u[i] - g_C[(size_t)i * NQ + j]) * INV_EPS;
        float mn = fmaxf(m, a);
        s = fmaf(s, fexp(m - mn), fexp(a - mn));
        m = mn;
    }
    __shared__ float sm[8][32], ss[8][32];
    sm[p][c] = m; ss[p][c] = s;
    __syncthreads();
    if (p == 0) {
        float M = sm[0][c], S = ss[0][c];
        #pragma unroll
        for (int w = 1; w < 8; w++) lse_combine(M, S, sm[w][c], ss[w][c]);
        float L = M + logf(S);
        g_v[j] = EPSR * (LOG_NU - L);
    }
}

// ---------------- convergence check (deterministic reduction) ----------------
__global__ void k_check() {
    if (g_done) return;
    __shared__ float sm[256];
    float s = 0.0f;
    for (int r = threadIdx.x; r < NS; r += 256) s += g_rowerr[r];
    sm[threadIdx.x] = s;
    __syncthreads();
    #pragma unroll
    for (int off = 128; off; off >>= 1) {
        if (threadIdx.x < off) sm[threadIdx.x] += sm[threadIdx.x + off];
        __syncthreads();
    }
    if (threadIdx.x == 0 && sm[0] < THRESHV) g_done = 1;
}

// ---------------- final row stats (max + inv sum) with converged v ----------------
__global__ __launch_bounds__(256) void k_stats() {
    int i = blockIdx.x;
    const float* Crow = g_C + (size_t)i * NQ;
    float m = -1e30f, s = 0.0f;
    #pragma unroll 4
    for (int j = threadIdx.x; j < NQ; j += 256) {
        float a  = (g_v[j] - Crow[j]) * INV_EPS;
        float mn = fmaxf(m, a);
        s = fmaf(s, fexp(m - mn), fexp(a - mn));
        m = mn;
    }
    lse_block_reduce(m, s);
    if (threadIdx.x == 0) {
        g_m[i]    = m;
        g_sinv[i] = 1.0f / s;
    }
}

// ---------------- transform C -> normalized transport weights (in place) ----------------
__global__ void k_weights() {
    int t   = blockIdx.x * blockDim.x + threadIdx.x;   // one float4 each
    int idx = t * 4;
    int i   = idx >> 13;        // / NQ
    int j   = idx & (NQ - 1);
    float mi = g_m[i], si = g_sinv[i];
    float4 c  = *reinterpret_cast<float4*>(&g_C[idx]);
    float4 vv = *reinterpret_cast<const float4*>(&g_v[j]);
    float4 w;
    w.x = fexp(fmaf(vv.x - c.x, INV_EPS, -mi)) * si;
    w.y = fexp(fmaf(vv.y - c.y, INV_EPS, -mi)) * si;
    w.z = fexp(fmaf(vv.z - c.z, INV_EPS, -mi)) * si;
    w.w = fexp(fmaf(vv.w - c.w, INV_EPS, -mi)) * si;
    *reinterpret_cast<float4*>(&g_C[idx]) = w;
}

// ---------------- out = W @ zq  (split-K fp32 GEMM NN, 64x64 tile) ----------------
__global__ __launch_bounds__(256) void k_out(const float* __restrict__ B) {
    __shared__ float As[16][64];
    __shared__ float Bs[16][64];
    int tx = threadIdx.x & 15, ty = threadIdx.x >> 4;
    int m0 = blockIdx.y * 64;
    int n0 = blockIdx.x * 64;
    int kbase = blockIdx.z * (NQ / SPLITK);
    float acc[4][4] = {};
    for (int k0 = kbase; k0 < kbase + NQ / SPLITK; k0 += 16) {
        {
            int r  = threadIdx.x >> 2, k4 = threadIdx.x & 3;
            float4 va = *reinterpret_cast<const float4*>(g_C + (size_t)(m0 + r) * NQ + k0 + k4 * 4);
            As[k4*4+0][r] = va.x; As[k4*4+1][r] = va.y; As[k4*4+2][r] = va.z; As[k4*4+3][r] = va.w;
            int kk = threadIdx.x >> 4, c4 = threadIdx.x & 15;
            float4 vb = *reinterpret_cast<const float4*>(B + (size_t)(k0 + kk) * DD + n0 + c4 * 4);
            *reinterpret_cast<float4*>(&Bs[kk][c4 * 4]) = vb;
        }
        __syncthreads();
        #pragma unroll
        for (int kk = 0; kk < 16; kk++) {
            float a[4], b[4];
            #pragma unroll
            for (int q = 0; q < 4; q++) { a[q] = As[kk][ty*4+q]; b[q] = Bs[kk][tx*4+q]; }
            #pragma unroll
            for (int ii = 0; ii < 4; ii++)
                #pragma unroll
                for (int jj = 0; jj < 4; jj++)
                    acc[ii][jj] = fmaf(a[ii], b[jj], acc[ii][jj]);
        }
        __syncthreads();
    }
    float* P = g_part + (size_t)blockIdx.z * NS * DD;
    #pragma unroll
    for (int ii = 0; ii < 4; ii++)
        #pragma unroll
        for (int jj = 0; jj < 4; jj++)
            P[(size_t)(m0 + ty*4 + ii) * DD + n0 + tx*4 + jj] = acc[ii][jj];
}

// ---------------- reduce split-K partials (deterministic order) ----------------
__global__ void k_reduce(float* __restrict__ out) {
    int t = blockIdx.x * blockDim.x + threadIdx.x;   // over NS*DD
    float s = 0.0f;
    #pragma unroll
    for (int q = 0; q < SPLITK; q++) s += g_part[(size_t)q * NS * DD + t];
    out[t] = s;
}

// ---------------- copy z_query to the second output slot ----------------
__global__ void k_copy(const float* __restrict__ zq, float* __restrict__ out) {
    int t = blockIdx.x * blockDim.x + threadIdx.x;   // one float4 each
    reinterpret_cast<float4*>(out)[t] = reinterpret_cast<const float4*>(zq)[t];
}

// ---------------- launch ----------------
extern "C" void kernel_launch(void* const* d_in, const int* in_sizes, int n_in,
                              void* d_out, int out_size) {
    const float* zs = (const float*)d_in[0];
    const float* zq = (const float*)d_in[1];
    if (n_in >= 2 && in_sizes[0] == NQ * DD) {   // defensive: order by size
        const float* t = zs; zs = zq; zq = t;
    }
    float* out = (float*)d_out;

    k_init<<<(NQ + 255) / 256, 256>>>();
    k_norms<<<(NS + NQ) / 8, 256>>>(zs, zq);
    k_cost<<<dim3(NQ / 128, NS / 128), 256>>>(zs, zq);

    for (int it = 0; it < MAX_ITER; it++) {
        k_update_u<<<NS, 256>>>();
        k_update_v<<<NQ / 32, 256>>>();
        k_check<<<1, 256>>>();
    }

    k_stats<<<NS, 256>>>();
    k_weights<<<(NS * NQ / 4) / 256, 256>>>();
    k_out<<<dim3(DD / 64, NS / 64, SPLITK), 256>>>(zq);
    k_reduce<<<(NS * DD) / 256, 256>>>(out);
    k_copy<<<(NQ * DD / 4) / 256, 256>>>(zq, out + NS * DD);
}

// round 4
// speedup vs baseline: 1.2618x; 1.2618x over previous
#include <cuda_runtime.h>
#include <math.h>
#include <stdint.h>

#define NS 1024
#define NQ 8192
#define DD 256
#define EPSR 0.05f
#define INV_EPS 20.0f
#define THRESHV 1e-3f
#define MAX_ITER 100
#define SPLITK 8
#define GRIDB 256          // persistent-kernel blocks (<= 2 per SM guaranteed resident)

// log(1/Ns + 1e-8), log(1/Nq + 1e-8)
#define LOG_MU  (-6.93146156565f)
#define LOG_NU  (-9.01083143063f)

// ---------------- device scratch (static, no allocations) ----------------
__device__ float g_C[(size_t)NS * NQ];
__device__ float g_u[NS];
__device__ float g_v[NQ];
__device__ float g_rowerr[NS];
__device__ float g_m[NS];
__device__ float g_sinv[NS];
__device__ float g_x2[NS];
__device__ float g_y2[NQ];
__device__ float g_part[(size_t)SPLITK * NS * DD];
__device__ int   g_done;
__device__ unsigned          g_arrive;
__device__ volatile unsigned g_gen;

// ---------------- fast exp: FMA-only (no MUFU) ----------------
__device__ __forceinline__ float fexp(float x) {
    x = fmaxf(x, -87.0f);
    float t = x * 1.4426950408889634f;
    float n = rintf(t);
    float f = t - n;
    float p = 1.540353039e-4f;
    p = fmaf(p, f, 1.333355815e-3f);
    p = fmaf(p, f, 9.618129108e-3f);
    p = fmaf(p, f, 5.550410866e-2f);
    p = fmaf(p, f, 2.402265070e-1f);
    p = fmaf(p, f, 6.931471806e-1f);
    p = fmaf(p, f, 1.0f);
    return p * __int_as_float(((int)n + 127) << 23);
}

__device__ __forceinline__ void lse_combine(float& m, float& s, float m2, float s2) {
    float mn = fmaxf(m, m2);
    s = s * fexp(m - mn) + s2 * fexp(m2 - mn);
    m = mn;
}

// ---------------- software grid barrier (all GRIDB blocks co-resident) ----------------
__device__ __forceinline__ void grid_barrier(unsigned target) {
    __syncthreads();
    if (threadIdx.x == 0) {
        __threadfence();
        unsigned prev = atomicAdd(&g_arrive, 1u);
        if (prev == GRIDB - 1) {
            g_arrive = 0;
            __threadfence();
            g_gen = target;
        } else {
            while (g_gen != target) { }
            __threadfence();
        }
    }
    __syncthreads();
}

// ---------------- init (start of every graph replay) ----------------
__global__ void k_init() {
    int t = blockIdx.x * blockDim.x + threadIdx.x;
    if (t < NS) g_u[t] = 0.0f;
    if (t < NQ) g_v[t] = 0.0f;
    if (t == 0) { g_done = 0; g_arrive = 0; g_gen = 0; }
}

// ---------------- squared norms ----------------
__global__ void k_norms(const float* __restrict__ zs, const float* __restrict__ zq) {
    int warp = (blockIdx.x * blockDim.x + threadIdx.x) >> 5;
    int lane = threadIdx.x & 31;
    if (warp >= NS + NQ) return;
    const float* row;
    float* out;
    if (warp < NS) { row = zs + (size_t)warp * DD;        out = g_x2 + warp; }
    else           { row = zq + (size_t)(warp - NS) * DD; out = g_y2 + (warp - NS); }
    float s = 0.0f;
    #pragma unroll
    for (int k = lane; k < DD; k += 32) { float v = row[k]; s = fmaf(v, v, s); }
    #pragma unroll
    for (int off = 16; off; off >>= 1) s += __shfl_down_sync(0xffffffffu, s, off);
    if (lane == 0) *out = s;
}

// ---------------- cost matrix: C = x2 + y2 - 2*A@B^T ----------------
__global__ __launch_bounds__(256) void k_cost(const float* __restrict__ A,
                                              const float* __restrict__ B) {
    __shared__ float As[16][128];
    __shared__ float Bs[16][128];
    int tx = threadIdx.x & 15, ty = threadIdx.x >> 4;
    int m0 = blockIdx.y * 128;
    int n0 = blockIdx.x * 128;
    float acc[8][8] = {};
    for (int k0 = 0; k0 < DD; k0 += 16) {
        #pragma unroll
        for (int t = 0; t < 2; t++) {
            int f  = threadIdx.x + t * 256;
            int r  = f >> 2, k4 = f & 3;
            float4 va = *reinterpret_cast<const float4*>(A + (size_t)(m0 + r) * DD + k0 + k4 * 4);
            As[k4*4+0][r] = va.x; As[k4*4+1][r] = va.y; As[k4*4+2][r] = va.z; As[k4*4+3][r] = va.w;
            float4 vb = *reinterpret_cast<const float4*>(B + (size_t)(n0 + r) * DD + k0 + k4 * 4);
            Bs[k4*4+0][r] = vb.x; Bs[k4*4+1][r] = vb.y; Bs[k4*4+2][r] = vb.z; Bs[k4*4+3][r] = vb.w;
        }
        __syncthreads();
        #pragma unroll
        for (int kk = 0; kk < 16; kk++) {
            float a[8], b[8];
            #pragma unroll
            for (int q = 0; q < 8; q++) { a[q] = As[kk][ty*8+q]; b[q] = Bs[kk][tx*8+q]; }
            #pragma unroll
            for (int ii = 0; ii < 8; ii++)
                #pragma unroll
                for (int jj = 0; jj < 8; jj++)
                    acc[ii][jj] = fmaf(a[ii], b[jj], acc[ii][jj]);
        }
        __syncthreads();
    }
    #pragma unroll
    for (int ii = 0; ii < 8; ii++) {
        int i = m0 + ty * 8 + ii;
        float x2 = g_x2[i];
        float* crow = g_C + (size_t)i * NQ + n0 + tx * 8;
        #pragma unroll
        for (int jj = 0; jj < 8; jj++) {
            int j = n0 + tx * 8 + jj;
            crow[jj] = x2 + g_y2[j] - 2.0f * acc[ii][jj];
        }
    }
}

// ---------------- persistent Sinkhorn loop ----------------
__global__ __launch_bounds__(256, 2) void k_sink() {
    __shared__ float smx[8];
    __shared__ float ssm[8];
    __shared__ float scm[8][33];
    __shared__ float scs[8][33];
    int tid  = threadIdx.x, bid = blockIdx.x;
    int lane = tid & 31,    w   = tid >> 5;
    unsigned bargen = 0;
    bool done = false;

    for (int it = 0; it < MAX_ITER; it++) {
        if (done) break;

        // ---- u phase: rows 4*bid .. 4*bid+3 (register-resident LSE) ----
        #pragma unroll 1
        for (int r = 0; r < 4; r++) {
            int i = bid * 4 + r;
            const float* Crow = g_C + (size_t)i * NQ;
            float a[32];
            #pragma unroll
            for (int k = 0; k < 8; k++) {
                float4 c  = *reinterpret_cast<const float4*>(Crow + tid * 4 + k * 1024);
                float4 vv = *reinterpret_cast<const float4*>(g_v  + tid * 4 + k * 1024);
                a[k*4+0] = (vv.x - c.x) * INV_EPS;
                a[k*4+1] = (vv.y - c.y) * INV_EPS;
                a[k*4+2] = (vv.z - c.z) * INV_EPS;
                a[k*4+3] = (vv.w - c.w) * INV_EPS;
            }
            // pairwise max tree (no clobber of a[])
            float m4[8];
            #pragma unroll
            for (int q = 0; q < 8; q++)
                m4[q] = fmaxf(fmaxf(a[4*q], a[4*q+1]), fmaxf(a[4*q+2], a[4*q+3]));
            float mx = fmaxf(fmaxf(fmaxf(m4[0], m4[1]), fmaxf(m4[2], m4[3])),
                             fmaxf(fmaxf(m4[4], m4[5]), fmaxf(m4[6], m4[7])));
            #pragma unroll
            for (int off = 16; off; off >>= 1)
                mx = fmaxf(mx, __shfl_xor_sync(0xffffffffu, mx, off));
            if (lane == 0) smx[w] = mx;
            __syncthreads();
            float m = smx[0];
            #pragma unroll
            for (int q = 1; q < 8; q++) m = fmaxf(m, smx[q]);
            // independent exp sums (4 accumulators)
            float s0 = 0, s1 = 0, s2 = 0, s3 = 0;
            #pragma unroll
            for (int q = 0; q < 8; q++) {
                s0 += fexp(a[4*q+0] - m);
                s1 += fexp(a[4*q+1] - m);
                s2 += fexp(a[4*q+2] - m);
                s3 += fexp(a[4*q+3] - m);
            }
            float s = (s0 + s1) + (s2 + s3);
            #pragma unroll
            for (int off = 16; off; off >>= 1)
                s += __shfl_down_sync(0xffffffffu, s, off);
            if (lane == 0) ssm[w] = s;
            __syncthreads();
            if (tid == 0) {
                float S = ((ssm[0]+ssm[1])+(ssm[2]+ssm[3])) + ((ssm[4]+ssm[5])+(ssm[6]+ssm[7]));
                float L = m + logf(S);
                float unew = EPSR * (LOG_MU - L);
                g_rowerr[i] = fabsf(unew - g_u[i]);
                g_u[i] = unew;
            }
            __syncthreads();
        }

        grid_barrier(++bargen);

        // ---- v phase: cols bid*32+lane, warp w covers rows [w*128, w*128+128) ----
        {
            int j = bid * 32 + lane;
            const float* colp = g_C + j;
            int ibase = w * 128;
            float m0 = -1e30f, m1 = -1e30f, m2 = -1e30f, m3 = -1e30f;
            #pragma unroll 8
            for (int ii = 0; ii < 128; ii += 4) {
                int i = ibase + ii;
                m0 = fmaxf(m0, (g_u[i+0] - colp[(size_t)(i+0) * NQ]) * INV_EPS);
                m1 = fmaxf(m1, (g_u[i+1] - colp[(size_t)(i+1) * NQ]) * INV_EPS);
                m2 = fmaxf(m2, (g_u[i+2] - colp[(size_t)(i+2) * NQ]) * INV_EPS);
                m3 = fmaxf(m3, (g_u[i+3] - colp[(size_t)(i+3) * NQ]) * INV_EPS);
            }
            float m = fmaxf(fmaxf(m0, m1), fmaxf(m2, m3));
            float s0 = 0, s1 = 0, s2 = 0, s3 = 0;
            #pragma unroll 8
            for (int ii = 0; ii < 128; ii += 4) {
                int i = ibase + ii;
                s0 += fexp(fmaf(g_u[i+0] - colp[(size_t)(i+0) * NQ], INV_EPS, -m));
                s1 += fexp(fmaf(g_u[i+1] - colp[(size_t)(i+1) * NQ], INV_EPS, -m));
                s2 += fexp(fmaf(g_u[i+2] - colp[(size_t)(i+2) * NQ], INV_EPS, -m));
                s3 += fexp(fmaf(g_u[i+3] - colp[(size_t)(i+3) * NQ], INV_EPS, -m));
            }
            float s = (s0 + s1) + (s2 + s3);
            scm[w][lane] = m; scs[w][lane] = s;
            __syncthreads();
            if (w == 0) {
                float M = scm[0][lane], S = scs[0][lane];
                #pragma unroll
                for (int q = 1; q < 8; q++) lse_combine(M, S, scm[q][lane], scs[q][lane]);
                g_v[j] = EPSR * (LOG_NU - (M + logf(S)));
            }
            // block 0: deterministic convergence check (rowerr from this iteration)
            if (bid == 0) {
                float e = g_rowerr[tid] + g_rowerr[tid + 256]
                        + g_rowerr[tid + 512] + g_rowerr[tid + 768];
                #pragma unroll
                for (int off = 16; off; off >>= 1)
                    e += __shfl_down_sync(0xffffffffu, e, off);
                if (lane == 0) ssm[w] = e;
                __syncthreads();
                if (tid == 0) {
                    float E = ((ssm[0]+ssm[1])+(ssm[2]+ssm[3])) + ((ssm[4]+ssm[5])+(ssm[6]+ssm[7]));
                    if (E < THRESHV) g_done = 1;
                }
            }
        }

        grid_barrier(++bargen);
        done = (*(volatile int*)&g_done) != 0;
    }
}

// ---------------- final row stats (max + inv sum) with converged v ----------------
__global__ __launch_bounds__(256) void k_stats() {
    int i = blockIdx.x;
    const float* Crow = g_C + (size_t)i * NQ;
    int tid = threadIdx.x, lane = tid & 31, w = tid >> 5;
    __shared__ float smx[8], ssm[8];
    float a[32];
    #pragma unroll
    for (int k = 0; k < 8; k++) {
        float4 c  = *reinterpret_cast<const float4*>(Crow + tid * 4 + k * 1024);
        float4 vv = *reinterpret_cast<const float4*>(g_v  + tid * 4 + k * 1024);
        a[k*4+0] = (vv.x - c.x) * INV_EPS;
        a[k*4+1] = (vv.y - c.y) * INV_EPS;
        a[k*4+2] = (vv.z - c.z) * INV_EPS;
        a[k*4+3] = (vv.w - c.w) * INV_EPS;
    }
    float m4[8];
    #pragma unroll
    for (int q = 0; q < 8; q++)
        m4[q] = fmaxf(fmaxf(a[4*q], a[4*q+1]), fmaxf(a[4*q+2], a[4*q+3]));
    float mx = fmaxf(fmaxf(fmaxf(m4[0], m4[1]), fmaxf(m4[2], m4[3])),
                     fmaxf(fmaxf(m4[4], m4[5]), fmaxf(m4[6], m4[7])));
    #pragma unroll
    for (int off = 16; off; off >>= 1)
        mx = fmaxf(mx, __shfl_xor_sync(0xffffffffu, mx, off));
    if (lane == 0) smx[w] = mx;
    __syncthreads();
    float m = smx[0];
    #pragma unroll
    for (int q = 1; q < 8; q++) m = fmaxf(m, smx[q]);
    float s0 = 0, s1 = 0, s2 = 0, s3 = 0;
    #pragma unroll
    for (int q = 0; q < 8; q++) {
        s0 += fexp(a[4*q+0] - m);
        s1 += fexp(a[4*q+1] - m);
        s2 += fexp(a[4*q+2] - m);
        s3 += fexp(a[4*q+3] - m);
    }
    float s = (s0 + s1) + (s2 + s3);
    #pragma unroll
    for (int off = 16; off; off >>= 1)
        s += __shfl_down_sync(0xffffffffu, s, off);
    if (lane == 0) ssm[w] = s;
    __syncthreads();
    if (tid == 0) {
        float S = ((ssm[0]+ssm[1])+(ssm[2]+ssm[3])) + ((ssm[4]+ssm[5])+(ssm[6]+ssm[7]));
        g_m[i]    = m;
        g_sinv[i] = 1.0f / S;
    }
}

// ---------------- out = softmax-weights(C) @ zq  (fused weights, split-K) ----------------
__global__ __launch_bounds__(256) void k_out(const float* __restrict__ B) {
    __shared__ float As[16][64];
    __shared__ float Bs[16][64];
    int tx = threadIdx.x & 15, ty = threadIdx.x >> 4;
    int m0 = blockIdx.y * 64;
    int n0 = blockIdx.x * 64;
    int kbase = blockIdx.z * (NQ / SPLITK);
    float acc[4][4] = {};
    for (int k0 = kbase; k0 < kbase + NQ / SPLITK; k0 += 16) {
        {
            int r  = threadIdx.x >> 2, k4 = threadIdx.x & 3;
            int row = m0 + r;
            float mi = g_m[row], si = g_sinv[row];
            float4 c  = *reinterpret_cast<const float4*>(g_C + (size_t)row * NQ + k0 + k4 * 4);
            float4 vv = *reinterpret_cast<const float4*>(g_v + k0 + k4 * 4);
            As[k4*4+0][r] = fexp(fmaf(vv.x - c.x, INV_EPS, -mi)) * si;
            As[k4*4+1][r] = fexp(fmaf(vv.y - c.y, INV_EPS, -mi)) * si;
            As[k4*4+2][r] = fexp(fmaf(vv.z - c.z, INV_EPS, -mi)) * si;
            As[k4*4+3][r] = fexp(fmaf(vv.w - c.w, INV_EPS, -mi)) * si;
            int kk = threadIdx.x >> 4, c4 = threadIdx.x & 15;
            float4 vb = *reinterpret_cast<const float4*>(B + (size_t)(k0 + kk) * DD + n0 + c4 * 4);
            *reinterpret_cast<float4*>(&Bs[kk][c4 * 4]) = vb;
        }
        __syncthreads();
        #pragma unroll
        for (int kk = 0; kk < 16; kk++) {
            float a[4], b[4];
            #pragma unroll
            for (int q = 0; q < 4; q++) { a[q] = As[kk][ty*4+q]; b[q] = Bs[kk][tx*4+q]; }
            #pragma unroll
            for (int ii = 0; ii < 4; ii++)
                #pragma unroll
                for (int jj = 0; jj < 4; jj++)
                    acc[ii][jj] = fmaf(a[ii], b[jj], acc[ii][jj]);
        }
        __syncthreads();
    }
    float* P = g_part + (size_t)blockIdx.z * NS * DD;
    #pragma unroll
    for (int ii = 0; ii < 4; ii++)
        #pragma unroll
        for (int jj = 0; jj < 4; jj++)
            P[(size_t)(m0 + ty*4 + ii) * DD + n0 + tx*4 + jj] = acc[ii][jj];
}

// ---------------- reduce split-K partials ----------------
__global__ void k_reduce(float* __restrict__ out) {
    int t = blockIdx.x * blockDim.x + threadIdx.x;
    float s = 0.0f;
    #pragma unroll
    for (int q = 0; q < SPLITK; q++) s += g_part[(size_t)q * NS * DD + t];
    out[t] = s;
}

// ---------------- copy z_query ----------------
__global__ void k_copy(const float* __restrict__ zq, float* __restrict__ out) {
    int t = blockIdx.x * blockDim.x + threadIdx.x;
    reinterpret_cast<float4*>(out)[t] = reinterpret_cast<const float4*>(zq)[t];
}

// ---------------- launch ----------------
extern "C" void kernel_launch(void* const* d_in, const int* in_sizes, int n_in,
                              void* d_out, int out_size) {
    const float* zs = (const float*)d_in[0];
    const float* zq = (const float*)d_in[1];
    if (n_in >= 2 && in_sizes[0] == NQ * DD) {
        const float* t = zs; zs = zq; zq = t;
    }
    float* out = (float*)d_out;

    k_init<<<(NQ + 255) / 256, 256>>>();
    k_norms<<<(NS + NQ) / 8, 256>>>(zs, zq);
    k_cost<<<dim3(NQ / 128, NS / 128), 256>>>(zs, zq);
    k_sink<<<GRIDB, 256>>>();
    k_stats<<<NS, 256>>>();
    k_out<<<dim3(DD / 64, NS / 64, SPLITK), 256>>>(zq);
    k_reduce<<<(NS * DD) / 256, 256>>>(out);
    k_copy<<<(NQ * DD / 4) / 256, 256>>>(zq, out + NS * DD);
}

// round 5
// speedup vs baseline: 1.6388x; 1.2988x over previous
#include <cuda_runtime.h>
#include <math.h>
#include <stdint.h>

#define NS 1024
#define NQ 8192
#define DD 256
#define EPSR 0.05f
#define INV_EPS 20.0f
#define THRESHV 1e-3f
#define MAX_ITER 100
#define SPLITK 8
#define GRIDB 256
#define TPB 512            // k_sink threads per block

// log2-domain scale: INV_EPS * log2(e)
#define K2   28.853900817779268f
#define LN2  0.6931471805599453f
#define LOG_MU  (-6.93146156565f)
#define LOG_NU  (-9.01083143063f)

// ---------------- device scratch (static, no allocations) ----------------
__device__ float g_C[(size_t)NS * NQ];
__device__ float g_u[NS];
__device__ float g_v[NQ];
__device__ float g_rowerr[NS];
__device__ float g_m[NS];       // log2-domain row max (a2 = (v-C)*K2)
__device__ float g_sinv[NS];
__device__ float g_x2[NS];
__device__ float g_y2[NQ];
__device__ float g_part[(size_t)SPLITK * NS * DD];
__device__ int   g_done;
__device__ unsigned          g_arrive;
__device__ volatile unsigned g_gen;

// ---------------- MUFU helpers ----------------
__device__ __forceinline__ float ex2f(float x) {
    float r; asm("ex2.approx.f32 %0, %1;" : "=f"(r) : "f"(x)); return r;
}
__device__ __forceinline__ float lg2f(float x) {
    float r; asm("lg2.approx.f32 %0, %1;" : "=f"(r) : "f"(x)); return r;
}

// ---------------- software grid barrier ----------------
__device__ __forceinline__ void grid_barrier(unsigned target) {
    __syncthreads();
    if (threadIdx.x == 0) {
        __threadfence();
        unsigned prev = atomicAdd(&g_arrive, 1u);
        if (prev == GRIDB - 1) {
            g_arrive = 0;
            __threadfence();
            g_gen = target;
        } else {
            int spins = 0;
            while (g_gen != target) {
                if (++spins > 16) __nanosleep(64);
            }
            __threadfence();
        }
    }
    __syncthreads();
}

// ---------------- init ----------------
__global__ void k_init() {
    int t = blockIdx.x * blockDim.x + threadIdx.x;
    if (t < NS) g_u[t] = 0.0f;
    if (t < NQ) g_v[t] = 0.0f;
    if (t == 0) { g_done = 0; g_arrive = 0; g_gen = 0; }
}

// ---------------- squared norms ----------------
__global__ void k_norms(const float* __restrict__ zs, const float* __restrict__ zq) {
    int warp = (blockIdx.x * blockDim.x + threadIdx.x) >> 5;
    int lane = threadIdx.x & 31;
    if (warp >= NS + NQ) return;
    const float* row;
    float* out;
    if (warp < NS) { row = zs + (size_t)warp * DD;        out = g_x2 + warp; }
    else           { row = zq + (size_t)(warp - NS) * DD; out = g_y2 + (warp - NS); }
    float s = 0.0f;
    #pragma unroll
    for (int k = lane; k < DD; k += 32) { float v = row[k]; s = fmaf(v, v, s); }
    #pragma unroll
    for (int off = 16; off; off >>= 1) s += __shfl_down_sync(0xffffffffu, s, off);
    if (lane == 0) *out = s;
}

// ---------------- cost matrix: C = x2 + y2 - 2*A@B^T ----------------
__global__ __launch_bounds__(256) void k_cost(const float* __restrict__ A,
                                              const float* __restrict__ B) {
    __shared__ float As[16][128];
    __shared__ float Bs[16][128];
    int tx = threadIdx.x & 15, ty = threadIdx.x >> 4;
    int m0 = blockIdx.y * 128;
    int n0 = blockIdx.x * 128;
    float acc[8][8] = {};
    for (int k0 = 0; k0 < DD; k0 += 16) {
        #pragma unroll
        for (int t = 0; t < 2; t++) {
            int f  = threadIdx.x + t * 256;
            int r  = f >> 2, k4 = f & 3;
            float4 va = *reinterpret_cast<const float4*>(A + (size_t)(m0 + r) * DD + k0 + k4 * 4);
            As[k4*4+0][r] = va.x; As[k4*4+1][r] = va.y; As[k4*4+2][r] = va.z; As[k4*4+3][r] = va.w;
            float4 vb = *reinterpret_cast<const float4*>(B + (size_t)(n0 + r) * DD + k0 + k4 * 4);
            Bs[k4*4+0][r] = vb.x; Bs[k4*4+1][r] = vb.y; Bs[k4*4+2][r] = vb.z; Bs[k4*4+3][r] = vb.w;
        }
        __syncthreads();
        #pragma unroll
        for (int kk = 0; kk < 16; kk++) {
            float a[8], b[8];
            #pragma unroll
            for (int q = 0; q < 8; q++) { a[q] = As[kk][ty*8+q]; b[q] = Bs[kk][tx*8+q]; }
            #pragma unroll
            for (int ii = 0; ii < 8; ii++)
                #pragma unroll
                for (int jj = 0; jj < 8; jj++)
                    acc[ii][jj] = fmaf(a[ii], b[jj], acc[ii][jj]);
        }
        __syncthreads();
    }
    #pragma unroll
    for (int ii = 0; ii < 8; ii++) {
        int i = m0 + ty * 8 + ii;
        float x2 = g_x2[i];
        float* crow = g_C + (size_t)i * NQ + n0 + tx * 8;
        #pragma unroll
        for (int jj = 0; jj < 8; jj++) {
            int j = n0 + tx * 8 + jj;
            crow[jj] = x2 + g_y2[j] - 2.0f * acc[ii][jj];
        }
    }
}

// ---------------- persistent Sinkhorn loop (log2 domain, MUFU ex2) ----------------
__global__ __launch_bounds__(TPB, 2) void k_sink() {
    __shared__ float mrow[4][17];     // per-row per-warp max partials (t = v - C)
    __shared__ float ssum[4][17];     // per-row per-warp exp-sum partials
    __shared__ float scm[16][33];     // v-phase per-warp max
    __shared__ float scs[16][33];     // v-phase per-warp sum
    __shared__ float u2s[NS];         // u * K2 cache
    __shared__ float sered[16];       // convergence scratch

    int tid  = threadIdx.x, bid = blockIdx.x;
    int lane = tid & 31,    w   = tid >> 5;     // 16 warps
    unsigned bargen = 0;
    bool done = false;

    for (int it = 0; it < MAX_ITER; it++) {
        if (done) break;

        // ======== u phase: rows 4*bid .. 4*bid+3 ========
        // pass 1: max of t = (v - C) per row
        #pragma unroll
        for (int r = 0; r < 4; r++) {
            int i = bid * 4 + r;
            const float* Crow = g_C + (size_t)i * NQ;
            float mx = -1e30f;
            #pragma unroll
            for (int k = 0; k < 4; k++) {
                float4 c  = *reinterpret_cast<const float4*>(Crow + tid * 4 + k * (TPB * 4));
                float4 vv = *reinterpret_cast<const float4*>(g_v  + tid * 4 + k * (TPB * 4));
                mx = fmaxf(mx, fmaxf(fmaxf(vv.x - c.x, vv.y - c.y),
                                     fmaxf(vv.z - c.z, vv.w - c.w)));
            }
            #pragma unroll
            for (int off = 16; off; off >>= 1)
                mx = fmaxf(mx, __shfl_xor_sync(0xffffffffu, mx, off));
            if (lane == 0) mrow[r][w] = mx;
        }
        __syncthreads();
        // pass 2: sum of ex2((t)*K2 - m2) per row (reload C from L1/L2)
        #pragma unroll
        for (int r = 0; r < 4; r++) {
            int i = bid * 4 + r;
            const float* Crow = g_C + (size_t)i * NQ;
            float mr = mrow[r][0];
            #pragma unroll
            for (int q = 1; q < 16; q++) mr = fmaxf(mr, mrow[r][q]);
            float m2 = mr * K2;
            float s0 = 0, s1 = 0, s2 = 0, s3 = 0;
            #pragma unroll
            for (int k = 0; k < 4; k++) {
                float4 c  = *reinterpret_cast<const float4*>(Crow + tid * 4 + k * (TPB * 4));
                float4 vv = *reinterpret_cast<const float4*>(g_v  + tid * 4 + k * (TPB * 4));
                s0 += ex2f(fmaf(vv.x - c.x, K2, -m2));
                s1 += ex2f(fmaf(vv.y - c.y, K2, -m2));
                s2 += ex2f(fmaf(vv.z - c.z, K2, -m2));
                s3 += ex2f(fmaf(vv.w - c.w, K2, -m2));
            }
            float s = (s0 + s1) + (s2 + s3);
            #pragma unroll
            for (int off = 16; off; off >>= 1)
                s += __shfl_down_sync(0xffffffffu, s, off);
            if (lane == 0) ssum[r][w] = s;
        }
        __syncthreads();
        if (tid < 4) {
            int i = bid * 4 + tid;
            float mr = mrow[tid][0];
            #pragma unroll
            for (int q = 1; q < 16; q++) mr = fmaxf(mr, mrow[tid][q]);
            float S = 0;
            #pragma unroll
            for (int q = 0; q < 16; q++) S += ssum[tid][q];
            float L    = LN2 * (mr * K2 + lg2f(S));
            float unew = EPSR * (LOG_MU - L);
            g_rowerr[i] = fabsf(unew - g_u[i]);
            g_u[i] = unew;
        }

        grid_barrier(++bargen);

        // ======== v phase: cols bid*32+lane; warp w rows [w*64, w*64+64) ========
        {
            // cache u*K2 in smem
            u2s[tid]       = g_u[tid]       * K2;
            u2s[tid + TPB] = g_u[tid + TPB] * K2;
            __syncthreads();

            int j = bid * 32 + lane;
            const float* colp = g_C + j;
            int ibase = w * 64;
            float m0 = -1e30f, m1 = -1e30f, m2v = -1e30f, m3 = -1e30f;
            #pragma unroll 4
            for (int ii = 0; ii < 64; ii += 4) {
                int i = ibase + ii;
                m0  = fmaxf(m0,  fmaf(colp[(size_t)(i+0) * NQ], -K2, u2s[i+0]));
                m1  = fmaxf(m1,  fmaf(colp[(size_t)(i+1) * NQ], -K2, u2s[i+1]));
                m2v = fmaxf(m2v, fmaf(colp[(size_t)(i+2) * NQ], -K2, u2s[i+2]));
                m3  = fmaxf(m3,  fmaf(colp[(size_t)(i+3) * NQ], -K2, u2s[i+3]));
            }
            float m2 = fmaxf(fmaxf(m0, m1), fmaxf(m2v, m3));
            float s0 = 0, s1 = 0, s2 = 0, s3 = 0;
            #pragma unroll 4
            for (int ii = 0; ii < 64; ii += 4) {
                int i = ibase + ii;
                s0 += ex2f(fmaf(colp[(size_t)(i+0) * NQ], -K2, u2s[i+0]) - m2);
                s1 += ex2f(fmaf(colp[(size_t)(i+1) * NQ], -K2, u2s[i+1]) - m2);
                s2 += ex2f(fmaf(colp[(size_t)(i+2) * NQ], -K2, u2s[i+2]) - m2);
                s3 += ex2f(fmaf(colp[(size_t)(i+3) * NQ], -K2, u2s[i+3]) - m2);
            }
            float s = (s0 + s1) + (s2 + s3);
            scm[w][lane] = m2; scs[w][lane] = s;
            __syncthreads();
            if (w == 0) {
                float M = scm[0][lane], S = scs[0][lane];
                #pragma unroll
                for (int q = 1; q < 16; q++) {
                    float m2q = scm[q][lane], s2q = scs[q][lane];
                    float mn = fmaxf(M, m2q);
                    S = S * ex2f(M - mn) + s2q * ex2f(m2q - mn);
                    M = mn;
                }
                g_v[j] = EPSR * (LOG_NU - LN2 * (M + lg2f(S)));
            }
            // block 0: convergence check on this iteration's rowerr
            if (bid == 0) {
                float e = g_rowerr[tid] + g_rowerr[tid + TPB];
                #pragma unroll
                for (int off = 16; off; off >>= 1)
                    e += __shfl_down_sync(0xffffffffu, e, off);
                if (lane == 0) sered[w] = e;
                __syncthreads();
                if (tid == 0) {
                    float E = 0;
                    #pragma unroll
                    for (int q = 0; q < 16; q++) E += sered[q];
                    if (E < THRESHV) g_done = 1;
                }
            }
        }

        grid_barrier(++bargen);
        done = (*(volatile int*)&g_done) != 0;
    }
}

// ---------------- final row stats: m2 (log2) + 1/S ----------------
__global__ __launch_bounds__(256) void k_stats() {
    int i = blockIdx.x;
    const float* Crow = g_C + (size_t)i * NQ;
    int tid = threadIdx.x, lane = tid & 31, w = tid >> 5;
    __shared__ float smx[8], ssm[8];
    float a[32];
    #pragma unroll
    for (int k = 0; k < 8; k++) {
        float4 c  = *reinterpret_cast<const float4*>(Crow + tid * 4 + k * 1024);
        float4 vv = *reinterpret_cast<const float4*>(g_v  + tid * 4 + k * 1024);
        a[k*4+0] = vv.x - c.x;
        a[k*4+1] = vv.y - c.y;
        a[k*4+2] = vv.z - c.z;
        a[k*4+3] = vv.w - c.w;
    }
    float m4[8];
    #pragma unroll
    for (int q = 0; q < 8; q++)
        m4[q] = fmaxf(fmaxf(a[4*q], a[4*q+1]), fmaxf(a[4*q+2], a[4*q+3]));
    float mx = fmaxf(fmaxf(fmaxf(m4[0], m4[1]), fmaxf(m4[2], m4[3])),
                     fmaxf(fmaxf(m4[4], m4[5]), fmaxf(m4[6], m4[7])));
    #pragma unroll
    for (int off = 16; off; off >>= 1)
        mx = fmaxf(mx, __shfl_xor_sync(0xffffffffu, mx, off));
    if (lane == 0) smx[w] = mx;
    __syncthreads();
    float m = smx[0];
    #pragma unroll
    for (int q = 1; q < 8; q++) m = fmaxf(m, smx[q]);
    float m2 = m * K2;
    float s0 = 0, s1 = 0, s2 = 0, s3 = 0;
    #pragma unroll
    for (int q = 0; q < 8; q++) {
        s0 += ex2f(fmaf(a[4*q+0], K2, -m2));
        s1 += ex2f(fmaf(a[4*q+1], K2, -m2));
        s2 += ex2f(fmaf(a[4*q+2], K2, -m2));
        s3 += ex2f(fmaf(a[4*q+3], K2, -m2));
    }
    float s = (s0 + s1) + (s2 + s3);
    #pragma unroll
    for (int off = 16; off; off >>= 1)
        s += __shfl_down_sync(0xffffffffu, s, off);
    if (lane == 0) ssm[w] = s;
    __syncthreads();
    if (tid == 0) {
        float S = ((ssm[0]+ssm[1])+(ssm[2]+ssm[3])) + ((ssm[4]+ssm[5])+(ssm[6]+ssm[7]));
        g_m[i]    = m2;         // log2 domain
        g_sinv[i] = 1.0f / S;
    }
}

// ---------------- out = softmax-weights(C) @ zq  (fused, split-K) ----------------
__global__ __launch_bounds__(256) void k_out(const float* __restrict__ B) {
    __shared__ float As[16][64];
    __shared__ float Bs[16][64];
    int tx = threadIdx.x & 15, ty = threadIdx.x >> 4;
    int m0 = blockIdx.y * 64;
    int n0 = blockIdx.x * 64;
    int kbase = blockIdx.z * (NQ / SPLITK);
    float acc[4][4] = {};
    for (int k0 = kbase; k0 < kbase + NQ / SPLITK; k0 += 16) {
        {
            int r  = threadIdx.x >> 2, k4 = threadIdx.x & 3;
            int row = m0 + r;
            float mi2 = g_m[row], si = g_sinv[row];
            float4 c  = *reinterpret_cast<const float4*>(g_C + (size_t)row * NQ + k0 + k4 * 4);
            float4 vv = *reinterpret_cast<const float4*>(g_v + k0 + k4 * 4);
            As[k4*4+0][r] = ex2f(fmaf(vv.x - c.x, K2, -mi2)) * si;
            As[k4*4+1][r] = ex2f(fmaf(vv.y - c.y, K2, -mi2)) * si;
            As[k4*4+2][r] = ex2f(fmaf(vv.z - c.z, K2, -mi2)) * si;
            As[k4*4+3][r] = ex2f(fmaf(vv.w - c.w, K2, -mi2)) * si;
            int kk = threadIdx.x >> 4, c4 = threadIdx.x & 15;
            float4 vb = *reinterpret_cast<const float4*>(B + (size_t)(k0 + kk) * DD + n0 + c4 * 4);
            *reinterpret_cast<float4*>(&Bs[kk][c4 * 4]) = vb;
        }
        __syncthreads();
        #pragma unroll
        for (int kk = 0; kk < 16; kk++) {
            float a[4], b[4];
            #pragma unroll
            for (int q = 0; q < 4; q++) { a[q] = As[kk][ty*4+q]; b[q] = Bs[kk][tx*4+q]; }
            #pragma unroll
            for (int ii = 0; ii < 4; ii++)
                #pragma unroll
                for (int jj = 0; jj < 4; jj++)
                    acc[ii][jj] = fmaf(a[ii], b[jj], acc[ii][jj]);
        }
        __syncthreads();
    }
    float* P = g_part + (size_t)blockIdx.z * NS * DD;
    #pragma unroll
    for (int ii = 0; ii < 4; ii++)
        #pragma unroll
        for (int jj = 0; jj < 4; jj++)
            P[(size_t)(m0 + ty*4 + ii) * DD + n0 + tx*4 + jj] = acc[ii][jj];
}

// ---------------- reduce split-K partials ----------------
__global__ void k_reduce(float* __restrict__ out) {
    int t = blockIdx.x * blockDim.x + threadIdx.x;
    float s = 0.0f;
    #pragma unroll
    for (int q = 0; q < SPLITK; q++) s += g_part[(size_t)q * NS * DD + t];
    out[t] = s;
}

// ---------------- copy z_query ----------------
__global__ void k_copy(const float* __restrict__ zq, float* __restrict__ out) {
    int t = blockIdx.x * blockDim.x + threadIdx.x;
    reinterpret_cast<float4*>(out)[t] = reinterpret_cast<const float4*>(zq)[t];
}

// ---------------- launch ----------------
extern "C" void kernel_launch(void* const* d_in, const int* in_sizes, int n_in,
                              void* d_out, int out_size) {
    const float* zs = (const float*)d_in[0];
    const float* zq = (const float*)d_in[1];
    if (n_in >= 2 && in_sizes[0] == NQ * DD) {
        const float* t = zs; zs = zq; zq = t;
    }
    float* out = (float*)d_out;

    k_init<<<(NQ + 255) / 256, 256>>>();
    k_norms<<<(NS + NQ) / 8, 256>>>(zs, zq);
    k_cost<<<dim3(NQ / 128, NS / 128), 256>>>(zs, zq);
    k_sink<<<GRIDB, TPB>>>();
    k_stats<<<NS, 256>>>();
    k_out<<<dim3(DD / 64, NS / 64, SPLITK), 256>>>(zq);
    k_reduce<<<(NS * DD) / 256, 256>>>(out);
    k_copy<<<(NQ * DD / 4) / 256, 256>>>(zq, out + NS * DD);
}

// round 6
// speedup vs baseline: 1.7865x; 1.0901x over previous
#include <cuda_runtime.h>
#include <math.h>
#include <stdint.h>

#define NS 1024
#define NQ 8192
#define DD 256
#define EPSR 0.05f
#define INV_EPS 20.0f
#define THRESHV 1e-3f
#define MAX_ITER 100
#define SPLITK 8
#define GRIDB 256
#define TPB 512

// log2-domain scale: INV_EPS * log2(e)
#define K2   28.853900817779268f
#define LN2  0.6931471805599453f
#define LOG_MU  (-6.93146156565f)
#define LOG_NU  (-9.01083143063f)

// ---------------- device scratch ----------------
__device__ float g_C[(size_t)NS * NQ];
__device__ float g_u[NS];
__device__ float g_v[NQ];
__device__ float g_rowerr[NS];
__device__ float g_mv[NQ];      // per-column true max of (u-C)*K2 from prev iter
__device__ float g_m[NS];       // final row max (log2 domain)
__device__ float g_sinv[NS];
__device__ float g_x2[NS];
__device__ float g_y2[NQ];
__device__ float g_part[(size_t)SPLITK * NS * DD];
__device__ int   g_done;
__device__ int   g_dmax[2];     // per-iteration max|du|*K2 as float bits (parity slots)
__device__ unsigned          g_arrive;
__device__ volatile unsigned g_gen;

// ---------------- MUFU helpers ----------------
__device__ __forceinline__ float ex2f(float x) {
    float r; asm("ex2.approx.f32 %0, %1;" : "=f"(r) : "f"(x)); return r;
}
__device__ __forceinline__ float lg2f(float x) {
    float r; asm("lg2.approx.f32 %0, %1;" : "=f"(r) : "f"(x)); return r;
}

// ---------------- software grid barrier ----------------
__device__ __forceinline__ void grid_barrier(unsigned target) {
    __syncthreads();
    if (threadIdx.x == 0) {
        __threadfence();
        unsigned prev = atomicAdd(&g_arrive, 1u);
        if (prev == GRIDB - 1) {
            g_arrive = 0;
            __threadfence();
            g_gen = target;
        } else {
            int spins = 0;
            while (g_gen != target) {
                if (++spins > 16) __nanosleep(64);
            }
            __threadfence();
        }
    }
    __syncthreads();
}

// ---------------- init ----------------
__global__ void k_init() {
    int t = blockIdx.x * blockDim.x + threadIdx.x;
    if (t < NS) g_u[t] = 0.0f;
    if (t < NQ) { g_v[t] = 0.0f; g_mv[t] = 0.0f; }
    if (t == 0) { g_done = 0; g_arrive = 0; g_gen = 0; g_dmax[0] = 0; g_dmax[1] = 0; }
}

// ---------------- squared norms ----------------
__global__ void k_norms(const float* __restrict__ zs, const float* __restrict__ zq) {
    int warp = (blockIdx.x * blockDim.x + threadIdx.x) >> 5;
    int lane = threadIdx.x & 31;
    if (warp >= NS + NQ) return;
    const float* row;
    float* out;
    if (warp < NS) { row = zs + (size_t)warp * DD;        out = g_x2 + warp; }
    else           { row = zq + (size_t)(warp - NS) * DD; out = g_y2 + (warp - NS); }
    float s = 0.0f;
    #pragma unroll
    for (int k = lane; k < DD; k += 32) { float v = row[k]; s = fmaf(v, v, s); }
    #pragma unroll
    for (int off = 16; off; off >>= 1) s += __shfl_down_sync(0xffffffffu, s, off);
    if (lane == 0) *out = s;
}

// ---------------- cost matrix: C = x2 + y2 - 2*A@B^T ----------------
__global__ __launch_bounds__(256) void k_cost(const float* __restrict__ A,
                                              const float* __restrict__ B) {
    __shared__ float As[16][128];
    __shared__ float Bs[16][128];
    int tx = threadIdx.x & 15, ty = threadIdx.x >> 4;
    int m0 = blockIdx.y * 128;
    int n0 = blockIdx.x * 128;
    float acc[8][8] = {};
    for (int k0 = 0; k0 < DD; k0 += 16) {
        #pragma unroll
        for (int t = 0; t < 2; t++) {
            int f  = threadIdx.x + t * 256;
            int r  = f >> 2, k4 = f & 3;
            float4 va = *reinterpret_cast<const float4*>(A + (size_t)(m0 + r) * DD + k0 + k4 * 4);
            As[k4*4+0][r] = va.x; As[k4*4+1][r] = va.y; As[k4*4+2][r] = va.z; As[k4*4+3][r] = va.w;
            float4 vb = *reinterpret_cast<const float4*>(B + (size_t)(n0 + r) * DD + k0 + k4 * 4);
            Bs[k4*4+0][r] = vb.x; Bs[k4*4+1][r] = vb.y; Bs[k4*4+2][r] = vb.z; Bs[k4*4+3][r] = vb.w;
        }
        __syncthreads();
        #pragma unroll
        for (int kk = 0; kk < 16; kk++) {
            float a[8], b[8];
            #pragma unroll
            for (int q = 0; q < 8; q++) { a[q] = As[kk][ty*8+q]; b[q] = Bs[kk][tx*8+q]; }
            #pragma unroll
            for (int ii = 0; ii < 8; ii++)
                #pragma unroll
                for (int jj = 0; jj < 8; jj++)
                    acc[ii][jj] = fmaf(a[ii], b[jj], acc[ii][jj]);
        }
        __syncthreads();
    }
    #pragma unroll
    for (int ii = 0; ii < 8; ii++) {
        int i = m0 + ty * 8 + ii;
        float x2 = g_x2[i];
        float* crow = g_C + (size_t)i * NQ + n0 + tx * 8;
        #pragma unroll
        for (int jj = 0; jj < 8; jj++) {
            int j = n0 + tx * 8 + jj;
            crow[jj] = x2 + g_y2[j] - 2.0f * acc[ii][jj];
        }
    }
}

// ---------------- persistent Sinkhorn loop ----------------
__global__ __launch_bounds__(TPB, 2) void k_sink() {
    __shared__ float mrow[4][17];
    __shared__ float ssum[4][17];
    __shared__ float scm[16][33];
    __shared__ float scs[16][33];
    __shared__ float u2s[NS];
    __shared__ float sered[16];

    int tid  = threadIdx.x, bid = blockIdx.x;
    int lane = tid & 31,    w   = tid >> 5;     // 16 warps
    unsigned bargen = 0;
    bool done = false;

    for (int it = 0; it < MAX_ITER; it++) {
        if (done) break;
        int par = it & 1;

        // ======== u phase: rows 4*bid..4*bid+3, register-resident (single C read) ========
        #pragma unroll 1
        for (int r = 0; r < 4; r++) {
            int i = bid * 4 + r;
            const float* Crow = g_C + (size_t)i * NQ;
            float a[16];
            #pragma unroll
            for (int k = 0; k < 4; k++) {
                float4 c  = *reinterpret_cast<const float4*>(Crow + tid * 4 + k * (TPB * 4));
                float4 vv = *reinterpret_cast<const float4*>(g_v  + tid * 4 + k * (TPB * 4));
                a[k*4+0] = vv.x - c.x;
                a[k*4+1] = vv.y - c.y;
                a[k*4+2] = vv.z - c.z;
                a[k*4+3] = vv.w - c.w;
            }
            float m4[4];
            #pragma unroll
            for (int q = 0; q < 4; q++)
                m4[q] = fmaxf(fmaxf(a[4*q], a[4*q+1]), fmaxf(a[4*q+2], a[4*q+3]));
            float mx = fmaxf(fmaxf(m4[0], m4[1]), fmaxf(m4[2], m4[3]));
            #pragma unroll
            for (int off = 16; off; off >>= 1)
                mx = fmaxf(mx, __shfl_xor_sync(0xffffffffu, mx, off));
            if (lane == 0) mrow[r][w] = mx;
            __syncthreads();
            float mr = mrow[r][0];
            #pragma unroll
            for (int q = 1; q < 16; q++) mr = fmaxf(mr, mrow[r][q]);
            float m2 = mr * K2;
            float s0 = 0, s1 = 0, s2 = 0, s3 = 0;
            #pragma unroll
            for (int q = 0; q < 4; q++) {
                s0 += ex2f(fmaf(a[4*q+0], K2, -m2));
                s1 += ex2f(fmaf(a[4*q+1], K2, -m2));
                s2 += ex2f(fmaf(a[4*q+2], K2, -m2));
                s3 += ex2f(fmaf(a[4*q+3], K2, -m2));
            }
            float s = (s0 + s1) + (s2 + s3);
            #pragma unroll
            for (int off = 16; off; off >>= 1)
                s += __shfl_down_sync(0xffffffffu, s, off);
            if (lane == 0) ssum[r][w] = s;
        }
        __syncthreads();
        float delta2 = 0.0f;
        if (tid < 4) {
            int i = bid * 4 + tid;
            float mr = mrow[tid][0];
            #pragma unroll
            for (int q = 1; q < 16; q++) mr = fmaxf(mr, mrow[tid][q]);
            float S = 0;
            #pragma unroll
            for (int q = 0; q < 16; q++) S += ssum[tid][q];
            float L    = LN2 * (mr * K2 + lg2f(S));
            float unew = EPSR * (LOG_MU - L);
            float uold = g_u[i];
            float d    = fabsf(unew - uold);
            g_rowerr[i] = d;
            g_u[i] = unew;
            delta2 = d * K2;
        }
        if (w == 0) {
            #pragma unroll
            for (int off = 16; off; off >>= 1)
                delta2 = fmaxf(delta2, __shfl_xor_sync(0xffffffffu, delta2, off));
            if (lane == 0) atomicMax(&g_dmax[par], __float_as_int(delta2));
        }

        grid_barrier(++bargen);

        // ======== v phase: cols bid*32+lane; warp w rows [w*64, w*64+64) ========
        {
            u2s[tid]       = g_u[tid]       * K2;
            u2s[tid + TPB] = g_u[tid + TPB] * K2;
            if (bid == 0 && tid == 0) g_dmax[1 - par] = 0;  // reset next-iter slot
            __syncthreads();

            float dmaxu2 = __int_as_float(g_dmax[par]);
            bool onepass = (it > 0) && (dmaxu2 <= 40.0f);   // grid-uniform branch

            int j = bid * 32 + lane;
            const float* colp = g_C + j;
            int ibase = w * 64;

            if (onepass) {
                // exact LSE with stale-max shift; track true max in same pass
                float m_est = g_mv[j] + dmaxu2;
                float mx0 = -1e30f, mx1 = -1e30f;
                float s0 = 0, s1 = 0, s2 = 0, s3 = 0;
                #pragma unroll 4
                for (int ii = 0; ii < 64; ii += 4) {
                    int i = ibase + ii;
                    float a0 = fmaf(colp[(size_t)(i+0) * NQ], -K2, u2s[i+0]);
                    float a1 = fmaf(colp[(size_t)(i+1) * NQ], -K2, u2s[i+1]);
                    float a2 = fmaf(colp[(size_t)(i+2) * NQ], -K2, u2s[i+2]);
                    float a3 = fmaf(colp[(size_t)(i+3) * NQ], -K2, u2s[i+3]);
                    mx0 = fmaxf(mx0, fmaxf(a0, a1));
                    mx1 = fmaxf(mx1, fmaxf(a2, a3));
                    s0 += ex2f(a0 - m_est);
                    s1 += ex2f(a1 - m_est);
                    s2 += ex2f(a2 - m_est);
                    s3 += ex2f(a3 - m_est);
                }
                scm[w][lane] = fmaxf(mx0, mx1);
                scs[w][lane] = (s0 + s1) + (s2 + s3);
                __syncthreads();
                if (w == 0) {
                    float M = scm[0][lane], S = scs[0][lane];
                    #pragma unroll
                    for (int q = 1; q < 16; q++) {
                        M = fmaxf(M, scm[q][lane]);
                        S += scs[q][lane];
                    }
                    g_mv[j] = M;
                    g_v[j]  = EPSR * (LOG_NU - LN2 * (m_est + lg2f(S)));
                }
            } else {
                // exact two-pass
                float mx0 = -1e30f, mx1 = -1e30f;
                #pragma unroll 4
                for (int ii = 0; ii < 64; ii += 4) {
                    int i = ibase + ii;
                    mx0 = fmaxf(mx0, fmaxf(fmaf(colp[(size_t)(i+0) * NQ], -K2, u2s[i+0]),
                                           fmaf(colp[(size_t)(i+1) * NQ], -K2, u2s[i+1])));
                    mx1 = fmaxf(mx1, fmaxf(fmaf(colp[(size_t)(i+2) * NQ], -K2, u2s[i+2]),
                                           fmaf(colp[(size_t)(i+3) * NQ], -K2, u2s[i+3])));
                }
                scm[w][lane] = fmaxf(mx0, mx1);
                __syncthreads();
                float M = scm[0][lane];
                #pragma unroll
                for (int q = 1; q < 16; q++) M = fmaxf(M, scm[q][lane]);
                float s0 = 0, s1 = 0, s2 = 0, s3 = 0;
                #pragma unroll 4
                for (int ii = 0; ii < 64; ii += 4) {
                    int i = ibase + ii;
                    s0 += ex2f(fmaf(colp[(size_t)(i+0) * NQ], -K2, u2s[i+0]) - M);
                    s1 += ex2f(fmaf(colp[(size_t)(i+1) * NQ], -K2, u2s[i+1]) - M);
                    s2 += ex2f(fmaf(colp[(size_t)(i+2) * NQ], -K2, u2s[i+2]) - M);
                    s3 += ex2f(fmaf(colp[(size_t)(i+3) * NQ], -K2, u2s[i+3]) - M);
                }
                scs[w][lane] = (s0 + s1) + (s2 + s3);
                __syncthreads();
                if (w == 0) {
                    float S = scs[0][lane];
                    #pragma unroll
                    for (int q = 1; q < 16; q++) S += scs[q][lane];
                    g_mv[j] = M;
                    g_v[j]  = EPSR * (LOG_NU - LN2 * (M + lg2f(S)));
                }
            }

            // block 0: convergence check on this iteration's rowerr
            if (bid == 0) {
                float e = g_rowerr[tid] + g_rowerr[tid + TPB];
                #pragma unroll
                for (int off = 16; off; off >>= 1)
                    e += __shfl_down_sync(0xffffffffu, e, off);
                if (lane == 0) sered[w] = e;
                __syncthreads();
                if (tid == 0) {
                    float E = 0;
                    #pragma unroll
                    for (int q = 0; q < 16; q++) E += sered[q];
                    if (E < THRESHV) g_done = 1;
                }
            }
        }

        grid_barrier(++bargen);
        done = (*(volatile int*)&g_done) != 0;
    }
}

// ---------------- final row stats: m2 (log2) + 1/S ----------------
__global__ __launch_bounds__(256) void k_stats() {
    int i = blockIdx.x;
    const float* Crow = g_C + (size_t)i * NQ;
    int tid = threadIdx.x, lane = tid & 31, w = tid >> 5;
    __shared__ float smx[8], ssm[8];
    float a[32];
    #pragma unroll
    for (int k = 0; k < 8; k++) {
        float4 c  = *reinterpret_cast<const float4*>(Crow + tid * 4 + k * 1024);
        float4 vv = *reinterpret_cast<const float4*>(g_v  + tid * 4 + k * 1024);
        a[k*4+0] = vv.x - c.x;
        a[k*4+1] = vv.y - c.y;
        a[k*4+2] = vv.z - c.z;
        a[k*4+3] = vv.w - c.w;
    }
    float m4[8];
    #pragma unroll
    for (int q = 0; q < 8; q++)
        m4[q] = fmaxf(fmaxf(a[4*q], a[4*q+1]), fmaxf(a[4*q+2], a[4*q+3]));
    float mx = fmaxf(fmaxf(fmaxf(m4[0], m4[1]), fmaxf(m4[2], m4[3])),
                     fmaxf(fmaxf(m4[4], m4[5]), fmaxf(m4[6], m4[7])));
    #pragma unroll
    for (int off = 16; off; off >>= 1)
        mx = fmaxf(mx, __shfl_xor_sync(0xffffffffu, mx, off));
    if (lane == 0) smx[w] = mx;
    __syncthreads();
    float m = smx[0];
    #pragma unroll
    for (int q = 1; q < 8; q++) m = fmaxf(m, smx[q]);
    float m2 = m * K2;
    float s0 = 0, s1 = 0, s2 = 0, s3 = 0;
    #pragma unroll
    for (int q = 0; q < 8; q++) {
        s0 += ex2f(fmaf(a[4*q+0], K2, -m2));
        s1 += ex2f(fmaf(a[4*q+1], K2, -m2));
        s2 += ex2f(fmaf(a[4*q+2], K2, -m2));
        s3 += ex2f(fmaf(a[4*q+3], K2, -m2));
    }
    float s = (s0 + s1) + (s2 + s3);
    #pragma unroll
    for (int off = 16; off; off >>= 1)
        s += __shfl_down_sync(0xffffffffu, s, off);
    if (lane == 0) ssm[w] = s;
    __syncthreads();
    if (tid == 0) {
        float S = ((ssm[0]+ssm[1])+(ssm[2]+ssm[3])) + ((ssm[4]+ssm[5])+(ssm[6]+ssm[7]));
        g_m[i]    = m2;
        g_sinv[i] = 1.0f / S;
    }
}

// ---------------- out = softmax-weights(C) @ zq  (fused, split-K) ----------------
__global__ __launch_bounds__(256) void k_out(const float* __restrict__ B) {
    __shared__ float As[16][64];
    __shared__ float Bs[16][64];
    int tx = threadIdx.x & 15, ty = threadIdx.x >> 4;
    int m0 = blockIdx.y * 64;
    int n0 = blockIdx.x * 64;
    int kbase = blockIdx.z * (NQ / SPLITK);
    float acc[4][4] = {};
    for (int k0 = kbase; k0 < kbase + NQ / SPLITK; k0 += 16) {
        {
            int r  = threadIdx.x >> 2, k4 = threadIdx.x & 3;
            int row = m0 + r;
            float mi2 = g_m[row], si = g_sinv[row];
            float4 c  = *reinterpret_cast<const float4*>(g_C + (size_t)row * NQ + k0 + k4 * 4);
            float4 vv = *reinterpret_cast<const float4*>(g_v + k0 + k4 * 4);
            As[k4*4+0][r] = ex2f(fmaf(vv.x - c.x, K2, -mi2)) * si;
            As[k4*4+1][r] = ex2f(fmaf(vv.y - c.y, K2, -mi2)) * si;
            As[k4*4+2][r] = ex2f(fmaf(vv.z - c.z, K2, -mi2)) * si;
            As[k4*4+3][r] = ex2f(fmaf(vv.w - c.w, K2, -mi2)) * si;
            int kk = threadIdx.x >> 4, c4 = threadIdx.x & 15;
            float4 vb = *reinterpret_cast<const float4*>(B + (size_t)(k0 + kk) * DD + n0 + c4 * 4);
            *reinterpret_cast<float4*>(&Bs[kk][c4 * 4]) = vb;
        }
        __syncthreads();
        #pragma unroll
        for (int kk = 0; kk < 16; kk++) {
            float a[4], b[4];
            #pragma unroll
            for (int q = 0; q < 4; q++) { a[q] = As[kk][ty*4+q]; b[q] = Bs[kk][tx*4+q]; }
            #pragma unroll
            for (int ii = 0; ii < 4; ii++)
                #pragma unroll
                for (int jj = 0; jj < 4; jj++)
                    acc[ii][jj] = fmaf(a[ii], b[jj], acc[ii][jj]);
        }
        __syncthreads();
    }
    float* P = g_part + (size_t)blockIdx.z * NS * DD;
    #pragma unroll
    for (int ii = 0; ii < 4; ii++)
        #pragma unroll
        for (int jj = 0; jj < 4; jj++)
            P[(size_t)(m0 + ty*4 + ii) * DD + n0 + tx*4 + jj] = acc[ii][jj];
}

// ---------------- reduce split-K partials ----------------
__global__ void k_reduce(float* __restrict__ out) {
    int t = blockIdx.x * blockDim.x + threadIdx.x;
    float s = 0.0f;
    #pragma unroll
    for (int q = 0; q < SPLITK; q++) s += g_part[(size_t)q * NS * DD + t];
    out[t] = s;
}

// ---------------- copy z_query ----------------
__global__ void k_copy(const float* __restrict__ zq, float* __restrict__ out) {
    int t = blockIdx.x * blockDim.x + threadIdx.x;
    reinterpret_cast<float4*>(out)[t] = reinterpret_cast<const float4*>(zq)[t];
}

// ---------------- launch ----------------
extern "C" void kernel_launch(void* const* d_in, const int* in_sizes, int n_in,
                              void* d_out, int out_size) {
    const float* zs = (const float*)d_in[0];
    const float* zq = (const float*)d_in[1];
    if (n_in >= 2 && in_sizes[0] == NQ * DD) {
        const float* t = zs; zs = zq; zq = t;
    }
    float* out = (float*)d_out;

    k_init<<<(NQ + 255) / 256, 256>>>();
    k_norms<<<(NS + NQ) / 8, 256>>>(zs, zq);
    k_cost<<<dim3(NQ / 128, NS / 128), 256>>>(zs, zq);
    k_sink<<<GRIDB, TPB>>>();
    k_stats<<<NS, 256>>>();
    k_out<<<dim3(DD / 64, NS / 64, SPLITK), 256>>>(zq);
    k_reduce<<<(NS * DD) / 256, 256>>>(out);
    k_copy<<<(NQ * DD / 4) / 256, 256>>>(zq, out + NS * DD);
}

// round 7
// speedup vs baseline: 2.0095x; 1.1248x over previous
#include <cuda_runtime.h>
#include <math.h>
#include <stdint.h>

#define NS 1024
#define NQ 8192
#define DD 256
#define EPSR 0.05f
#define INV_EPS 20.0f
#define THRESHV 1e-3f
#define MAX_ITER 100
#define SPLITK 8
#define GRIDB 256
#define TPB 512

// log2-domain scale: INV_EPS * log2(e)
#define K2   28.853900817779268f
#define LN2  0.6931471805599453f
#define LOG_MU  (-6.93146156565f)
#define LOG_NU  (-9.01083143063f)

// ---------------- device scratch ----------------
__device__ float g_C[(size_t)NS * NQ];
__device__ float g_u[NS];
__device__ float g_v[NQ];
__device__ float g_rowerr[NS];
__device__ float g_mu[NS];      // per-row true max of (v-C), plain units
__device__ float g_mv[NQ];      // per-col true max of (u-C)*K2
__device__ float g_m[NS];       // final row shift (log2 domain) for k_out
__device__ float g_sinv[NS];
__device__ float g_x2[NS];
__device__ float g_y2[NQ];
__device__ float g_part[(size_t)SPLITK * NS * DD];
__device__ int   g_done;
__device__ int   g_dmax[2];     // max|du|*K2 bits, parity slots
__device__ int   g_dmaxv[2];    // max|dv|*K2 bits, parity slots
__device__ unsigned          g_arrive;
__device__ volatile unsigned g_gen;

// ---------------- MUFU helpers ----------------
__device__ __forceinline__ float ex2f(float x) {
    float r; asm("ex2.approx.f32 %0, %1;" : "=f"(r) : "f"(x)); return r;
}
__device__ __forceinline__ float lg2f(float x) {
    float r; asm("lg2.approx.f32 %0, %1;" : "=f"(r) : "f"(x)); return r;
}

// ---------------- software grid barrier ----------------
__device__ __forceinline__ void grid_barrier(unsigned target) {
    __syncthreads();
    if (threadIdx.x == 0) {
        __threadfence();
        unsigned prev = atomicAdd(&g_arrive, 1u);
        if (prev == GRIDB - 1) {
            g_arrive = 0;
            __threadfence();
            g_gen = target;
        } else {
            int spins = 0;
            while (g_gen != target) {
                if (++spins > 64) __nanosleep(32);
            }
            __threadfence();
        }
    }
    __syncthreads();
}

// ---------------- init ----------------
__global__ void k_init() {
    int t = blockIdx.x * blockDim.x + threadIdx.x;
    if (t < NS) { g_u[t] = 0.0f; g_mu[t] = 0.0f; }
    if (t < NQ) { g_v[t] = 0.0f; g_mv[t] = 0.0f; }
    if (t == 0) {
        g_done = 0; g_arrive = 0; g_gen = 0;
        g_dmax[0] = 0; g_dmax[1] = 0; g_dmaxv[0] = 0; g_dmaxv[1] = 0;
    }
}

// ---------------- squared norms ----------------
__global__ void k_norms(const float* __restrict__ zs, const float* __restrict__ zq) {
    int warp = (blockIdx.x * blockDim.x + threadIdx.x) >> 5;
    int lane = threadIdx.x & 31;
    if (warp >= NS + NQ) return;
    const float* row;
    float* out;
    if (warp < NS) { row = zs + (size_t)warp * DD;        out = g_x2 + warp; }
    else           { row = zq + (size_t)(warp - NS) * DD; out = g_y2 + (warp - NS); }
    float s = 0.0f;
    #pragma unroll
    for (int k = lane; k < DD; k += 32) { float v = row[k]; s = fmaf(v, v, s); }
    #pragma unroll
    for (int off = 16; off; off >>= 1) s += __shfl_down_sync(0xffffffffu, s, off);
    if (lane == 0) *out = s;
}

// ---------------- cost matrix: C = x2 + y2 - 2*A@B^T ----------------
__global__ __launch_bounds__(256) void k_cost(const float* __restrict__ A,
                                              const float* __restrict__ B) {
    __shared__ float As[16][128];
    __shared__ float Bs[16][128];
    int tx = threadIdx.x & 15, ty = threadIdx.x >> 4;
    int m0 = blockIdx.y * 128;
    int n0 = blockIdx.x * 128;
    float acc[8][8] = {};
    for (int k0 = 0; k0 < DD; k0 += 16) {
        #pragma unroll
        for (int t = 0; t < 2; t++) {
            int f  = threadIdx.x + t * 256;
            int r  = f >> 2, k4 = f & 3;
            float4 va = *reinterpret_cast<const float4*>(A + (size_t)(m0 + r) * DD + k0 + k4 * 4);
            As[k4*4+0][r] = va.x; As[k4*4+1][r] = va.y; As[k4*4+2][r] = va.z; As[k4*4+3][r] = va.w;
            float4 vb = *reinterpret_cast<const float4*>(B + (size_t)(n0 + r) * DD + k0 + k4 * 4);
            Bs[k4*4+0][r] = vb.x; Bs[k4*4+1][r] = vb.y; Bs[k4*4+2][r] = vb.z; Bs[k4*4+3][r] = vb.w;
        }
        __syncthreads();
        #pragma unroll
        for (int kk = 0; kk < 16; kk++) {
            float a[8], b[8];
            #pragma unroll
            for (int q = 0; q < 8; q++) { a[q] = As[kk][ty*8+q]; b[q] = Bs[kk][tx*8+q]; }
            #pragma unroll
            for (int ii = 0; ii < 8; ii++)
                #pragma unroll
                for (int jj = 0; jj < 8; jj++)
                    acc[ii][jj] = fmaf(a[ii], b[jj], acc[ii][jj]);
        }
        __syncthreads();
    }
    #pragma unroll
    for (int ii = 0; ii < 8; ii++) {
        int i = m0 + ty * 8 + ii;
        float x2 = g_x2[i];
        float* crow = g_C + (size_t)i * NQ + n0 + tx * 8;
        #pragma unroll
        for (int jj = 0; jj < 8; jj++) {
            int j = n0 + tx * 8 + jj;
            crow[jj] = x2 + g_y2[j] - 2.0f * acc[ii][jj];
        }
    }
}

// ---------------- persistent Sinkhorn loop + fused stats epilogue ----------------
__global__ __launch_bounds__(TPB, 2) void k_sink() {
    __shared__ float mrow[4][17];
    __shared__ float ssum[4][17];
    __shared__ float scm[16][33];
    __shared__ float scs[16][33];
    __shared__ float u2s[NS];
    __shared__ float sered[16];

    int tid  = threadIdx.x, bid = blockIdx.x;
    int lane = tid & 31,    w   = tid >> 5;     // 16 warps
    unsigned bargen = 0;
    bool done = false;
    int i0 = bid * 4;
    const float* C0 = g_C + (size_t)i0 * NQ;

    for (int it = 0; it < MAX_ITER; it++) {
        if (done) break;
        int par = it & 1;

        // ======== u phase: rows i0..i0+3 ========
        float dmv2 = __int_as_float(g_dmaxv[1 - par]);   // from prev v-phase
        bool onepass_u = (it > 0) && (dmv2 <= 20.0f);

        if (onepass_u) {
            // single streaming pass: shift by stale max bound, track true max
            float me2_0 = fmaf(g_mu[i0+0], K2, dmv2);
            float me2_1 = fmaf(g_mu[i0+1], K2, dmv2);
            float me2_2 = fmaf(g_mu[i0+2], K2, dmv2);
            float me2_3 = fmaf(g_mu[i0+3], K2, dmv2);
            float mx[4] = {-1e30f, -1e30f, -1e30f, -1e30f};
            float ss[4] = {0, 0, 0, 0};
            #pragma unroll
            for (int k = 0; k < 4; k++) {
                int off = tid * 4 + k * 2048;
                float4 vv = *reinterpret_cast<const float4*>(g_v + off);
                float4 c0 = *reinterpret_cast<const float4*>(C0 + off);
                float4 c1 = *reinterpret_cast<const float4*>(C0 + NQ + off);
                float4 c2 = *reinterpret_cast<const float4*>(C0 + 2 * NQ + off);
                float4 c3 = *reinterpret_cast<const float4*>(C0 + 3 * NQ + off);
                {
                    float a0 = vv.x - c0.x, a1 = vv.y - c0.y, a2 = vv.z - c0.z, a3 = vv.w - c0.w;
                    mx[0] = fmaxf(mx[0], fmaxf(fmaxf(a0, a1), fmaxf(a2, a3)));
                    ss[0] += (ex2f(fmaf(a0, K2, -me2_0)) + ex2f(fmaf(a1, K2, -me2_0)))
                           + (ex2f(fmaf(a2, K2, -me2_0)) + ex2f(fmaf(a3, K2, -me2_0)));
                }
                {
                    float a0 = vv.x - c1.x, a1 = vv.y - c1.y, a2 = vv.z - c1.z, a3 = vv.w - c1.w;
                    mx[1] = fmaxf(mx[1], fmaxf(fmaxf(a0, a1), fmaxf(a2, a3)));
                    ss[1] += (ex2f(fmaf(a0, K2, -me2_1)) + ex2f(fmaf(a1, K2, -me2_1)))
                           + (ex2f(fmaf(a2, K2, -me2_1)) + ex2f(fmaf(a3, K2, -me2_1)));
                }
                {
                    float a0 = vv.x - c2.x, a1 = vv.y - c2.y, a2 = vv.z - c2.z, a3 = vv.w - c2.w;
                    mx[2] = fmaxf(mx[2], fmaxf(fmaxf(a0, a1), fmaxf(a2, a3)));
                    ss[2] += (ex2f(fmaf(a0, K2, -me2_2)) + ex2f(fmaf(a1, K2, -me2_2)))
                           + (ex2f(fmaf(a2, K2, -me2_2)) + ex2f(fmaf(a3, K2, -me2_2)));
                }
                {
                    float a0 = vv.x - c3.x, a1 = vv.y - c3.y, a2 = vv.z - c3.z, a3 = vv.w - c3.w;
                    mx[3] = fmaxf(mx[3], fmaxf(fmaxf(a0, a1), fmaxf(a2, a3)));
                    ss[3] += (ex2f(fmaf(a0, K2, -me2_3)) + ex2f(fmaf(a1, K2, -me2_3)))
                           + (ex2f(fmaf(a2, K2, -me2_3)) + ex2f(fmaf(a3, K2, -me2_3)));
                }
            }
            #pragma unroll
            for (int r = 0; r < 4; r++) {
                float m = mx[r], s = ss[r];
                #pragma unroll
                for (int off = 16; off; off >>= 1) {
                    m = fmaxf(m, __shfl_xor_sync(0xffffffffu, m, off));
                    s += __shfl_xor_sync(0xffffffffu, s, off);
                }
                if (lane == 0) { mrow[r][w] = m; ssum[r][w] = s; }
            }
            __syncthreads();
            float delta2 = 0.0f;
            if (tid < 4) {
                int i = i0 + tid;
                float me2 = fmaf(g_mu[i], K2, dmv2);
                float mr = mrow[tid][0];
                float S  = ssum[tid][0];
                #pragma unroll
                for (int q = 1; q < 16; q++) { mr = fmaxf(mr, mrow[tid][q]); S += ssum[tid][q]; }
                float L    = LN2 * (me2 + lg2f(S));
                float unew = EPSR * (LOG_MU - L);
                float d    = fabsf(unew - g_u[i]);
                g_rowerr[i] = d;
                g_u[i]  = unew;
                g_mu[i] = mr;
                delta2 = d * K2;
            }
            if (w == 0) {
                #pragma unroll
                for (int off = 16; off; off >>= 1)
                    delta2 = fmaxf(delta2, __shfl_xor_sync(0xffffffffu, delta2, off));
                if (lane == 0) atomicMax(&g_dmax[par], __float_as_int(delta2));
            }
        } else {
            // exact two-pass streaming (early iterations only)
            float mx[4] = {-1e30f, -1e30f, -1e30f, -1e30f};
            #pragma unroll
            for (int k = 0; k < 4; k++) {
                int off = tid * 4 + k * 2048;
                float4 vv = *reinterpret_cast<const float4*>(g_v + off);
                #pragma unroll
                for (int r = 0; r < 4; r++) {
                    float4 c = *reinterpret_cast<const float4*>(C0 + (size_t)r * NQ + off);
                    mx[r] = fmaxf(mx[r], fmaxf(fmaxf(vv.x - c.x, vv.y - c.y),
                                               fmaxf(vv.z - c.z, vv.w - c.w)));
                }
            }
            #pragma unroll
            for (int r = 0; r < 4; r++) {
                float m = mx[r];
                #pragma unroll
                for (int off = 16; off; off >>= 1)
                    m = fmaxf(m, __shfl_xor_sync(0xffffffffu, m, off));
                if (lane == 0) mrow[r][w] = m;
            }
            __syncthreads();
            float rm2[4];
            #pragma unroll
            for (int r = 0; r < 4; r++) {
                float mr = mrow[r][0];
                #pragma unroll
                for (int q = 1; q < 16; q++) mr = fmaxf(mr, mrow[r][q]);
                rm2[r] = mr * K2;
                if (tid == r) g_mu[i0 + r] = mr;   // plain units
            }
            float ss[4] = {0, 0, 0, 0};
            #pragma unroll
            for (int k = 0; k < 4; k++) {
                int off = tid * 4 + k * 2048;
                float4 vv = *reinterpret_cast<const float4*>(g_v + off);
                #pragma unroll
                for (int r = 0; r < 4; r++) {
                    float4 c = *reinterpret_cast<const float4*>(C0 + (size_t)r * NQ + off);
                    ss[r] += (ex2f(fmaf(vv.x - c.x, K2, -rm2[r])) + ex2f(fmaf(vv.y - c.y, K2, -rm2[r])))
                           + (ex2f(fmaf(vv.z - c.z, K2, -rm2[r])) + ex2f(fmaf(vv.w - c.w, K2, -rm2[r])));
                }
            }
            #pragma unroll
            for (int r = 0; r < 4; r++) {
                float s = ss[r];
                #pragma unroll
                for (int off = 16; off; off >>= 1)
                    s += __shfl_xor_sync(0xffffffffu, s, off);
                if (lane == 0) ssum[r][w] = s;
            }
            __syncthreads();
            float delta2 = 0.0f;
            if (tid < 4) {
                int i = i0 + tid;
                float S = ssum[tid][0];
                #pragma unroll
                for (int q = 1; q < 16; q++) S += ssum[tid][q];
                float L    = LN2 * (rm2[tid] + lg2f(S));
                float unew = EPSR * (LOG_MU - L);
                float d    = fabsf(unew - g_u[i]);
                g_rowerr[i] = d;
                g_u[i] = unew;
                delta2 = d * K2;
            }
            if (w == 0) {
                #pragma unroll
                for (int off = 16; off; off >>= 1)
                    delta2 = fmaxf(delta2, __shfl_xor_sync(0xffffffffu, delta2, off));
                if (lane == 0) atomicMax(&g_dmax[par], __float_as_int(delta2));
            }
        }

        grid_barrier(++bargen);

        // ======== v phase: cols bid*32+lane; warp w rows [w*64, w*64+64) ========
        {
            u2s[tid]       = g_u[tid]       * K2;
            u2s[tid + TPB] = g_u[tid + TPB] * K2;
            if (bid == 0 && tid == 0) { g_dmax[1 - par] = 0; g_dmaxv[1 - par] = 0; }
            __syncthreads();

            float dmaxu2 = __int_as_float(g_dmax[par]);
            bool onepass = (it > 0) && (dmaxu2 <= 40.0f);

            int j = bid * 32 + lane;
            const float* colp = g_C + j;
            int ibase = w * 64;
            float vold = 0.0f, vnew = 0.0f;

            if (onepass) {
                float m_est = g_mv[j] + dmaxu2;
                float mx0 = -1e30f, mx1 = -1e30f;
                float s0 = 0, s1 = 0, s2 = 0, s3 = 0;
                float c8[8];
                #pragma unroll
                for (int st = 0; st < 8; st++) {
                    int i = ibase + st * 8;
                    #pragma unroll
                    for (int q = 0; q < 8; q++)
                        c8[q] = colp[(size_t)(i + q) * NQ];
                    float a0 = fmaf(c8[0], -K2, u2s[i+0]);
                    float a1 = fmaf(c8[1], -K2, u2s[i+1]);
                    float a2 = fmaf(c8[2], -K2, u2s[i+2]);
                    float a3 = fmaf(c8[3], -K2, u2s[i+3]);
                    float a4 = fmaf(c8[4], -K2, u2s[i+4]);
                    float a5 = fmaf(c8[5], -K2, u2s[i+5]);
                    float a6 = fmaf(c8[6], -K2, u2s[i+6]);
                    float a7 = fmaf(c8[7], -K2, u2s[i+7]);
                    mx0 = fmaxf(mx0, fmaxf(fmaxf(a0, a1), fmaxf(a2, a3)));
                    mx1 = fmaxf(mx1, fmaxf(fmaxf(a4, a5), fmaxf(a6, a7)));
                    s0 += ex2f(a0 - m_est) + ex2f(a4 - m_est);
                    s1 += ex2f(a1 - m_est) + ex2f(a5 - m_est);
                    s2 += ex2f(a2 - m_est) + ex2f(a6 - m_est);
                    s3 += ex2f(a3 - m_est) + ex2f(a7 - m_est);
                }
                scm[w][lane] = fmaxf(mx0, mx1);
                scs[w][lane] = (s0 + s1) + (s2 + s3);
                __syncthreads();
                if (w == 0) {
                    float M = scm[0][lane], S = scs[0][lane];
                    #pragma unroll
                    for (int q = 1; q < 16; q++) {
                        M = fmaxf(M, scm[q][lane]);
                        S += scs[q][lane];
                    }
                    g_mv[j] = M;
                    vold = g_v[j];
                    vnew = EPSR * (LOG_NU - LN2 * (m_est + lg2f(S)));
                    g_v[j] = vnew;
                }
            } else {
                float mx0 = -1e30f, mx1 = -1e30f;
                float c8[8];
                #pragma unroll
                for (int st = 0; st < 8; st++) {
                    int i = ibase + st * 8;
                    #pragma unroll
                    for (int q = 0; q < 8; q++)
                        c8[q] = colp[(size_t)(i + q) * NQ];
                    mx0 = fmaxf(mx0, fmaxf(fmaxf(fmaf(c8[0], -K2, u2s[i+0]), fmaf(c8[1], -K2, u2s[i+1])),
                                           fmaxf(fmaf(c8[2], -K2, u2s[i+2]), fmaf(c8[3], -K2, u2s[i+3]))));
                    mx1 = fmaxf(mx1, fmaxf(fmaxf(fmaf(c8[4], -K2, u2s[i+4]), fmaf(c8[5], -K2, u2s[i+5])),
                                           fmaxf(fmaf(c8[6], -K2, u2s[i+6]), fmaf(c8[7], -K2, u2s[i+7]))));
                }
                scm[w][lane] = fmaxf(mx0, mx1);
                __syncthreads();
                float M = scm[0][lane];
                #pragma unroll
                for (int q = 1; q < 16; q++) M = fmaxf(M, scm[q][lane]);
                float s0 = 0, s1 = 0, s2 = 0, s3 = 0;
                #pragma unroll
                for (int st = 0; st < 8; st++) {
                    int i = ibase + st * 8;
                    #pragma unroll
                    for (int q = 0; q < 8; q++)
                        c8[q] = colp[(size_t)(i + q) * NQ];
                    s0 += ex2f(fmaf(c8[0], -K2, u2s[i+0]) - M) + ex2f(fmaf(c8[4], -K2, u2s[i+4]) - M);
                    s1 += ex2f(fmaf(c8[1], -K2, u2s[i+1]) - M) + ex2f(fmaf(c8[5], -K2, u2s[i+5]) - M);
                    s2 += ex2f(fmaf(c8[2], -K2, u2s[i+2]) - M) + ex2f(fmaf(c8[6], -K2, u2s[i+6]) - M);
                    s3 += ex2f(fmaf(c8[3], -K2, u2s[i+3]) - M) + ex2f(fmaf(c8[7], -K2, u2s[i+7]) - M);
                }
                scs[w][lane] = (s0 + s1) + (s2 + s3);
                __syncthreads();
                if (w == 0) {
                    float S = scs[0][lane];
                    #pragma unroll
                    for (int q = 1; q < 16; q++) S += scs[q][lane];
                    g_mv[j] = M;
                    vold = g_v[j];
                    vnew = EPSR * (LOG_NU - LN2 * (M + lg2f(S)));
                    g_v[j] = vnew;
                }
            }

            // track max |dv|*K2 for next u-phase (w==0 lanes hold vold/vnew)
            if (w == 0) {
                float dv2 = fabsf(vnew - vold) * K2;
                #pragma unroll
                for (int off = 16; off; off >>= 1)
                    dv2 = fmaxf(dv2, __shfl_xor_sync(0xffffffffu, dv2, off));
                if (lane == 0) atomicMax(&g_dmaxv[par], __float_as_int(dv2));
            }

            // block 0: convergence check
            if (bid == 0) {
                float e = g_rowerr[tid] + g_rowerr[tid + TPB];
                #pragma unroll
                for (int off = 16; off; off >>= 1)
                    e += __shfl_down_sync(0xffffffffu, e, off);
                if (lane == 0) sered[w] = e;
                __syncthreads();
                if (tid == 0) {
                    float E = 0;
                    #pragma unroll
                    for (int q = 0; q < 16; q++) E += sered[q];
                    if (E < THRESHV) g_done = 1;
                }
            }
        }

        grid_barrier(++bargen);
        done = (*(volatile int*)&g_done) != 0;
    }

    // ======== fused stats epilogue: exact two-pass with FINAL v ========
    {
        float mx[4] = {-1e30f, -1e30f, -1e30f, -1e30f};
        #pragma unroll
        for (int k = 0; k < 4; k++) {
            int off = tid * 4 + k * 2048;
            float4 vv = *reinterpret_cast<const float4*>(g_v + off);
            #pragma unroll
            for (int r = 0; r < 4; r++) {
                float4 c = *reinterpret_cast<const float4*>(C0 + (size_t)r * NQ + off);
                mx[r] = fmaxf(mx[r], fmaxf(fmaxf(vv.x - c.x, vv.y - c.y),
                                           fmaxf(vv.z - c.z, vv.w - c.w)));
            }
        }
        #pragma unroll
        for (int r = 0; r < 4; r++) {
            float m = mx[r];
            #pragma unroll
            for (int off = 16; off; off >>= 1)
                m = fmaxf(m, __shfl_xor_sync(0xffffffffu, m, off));
            if (lane == 0) mrow[r][w] = m;
        }
        __syncthreads();
        float rm2[4];
        #pragma unroll
        for (int r = 0; r < 4; r++) {
            float mr = mrow[r][0];
            #pragma unroll
            for (int q = 1; q < 16; q++) mr = fmaxf(mr, mrow[r][q]);
            rm2[r] = mr * K2;
        }
        float ss[4] = {0, 0, 0, 0};
        #pragma unroll
        for (int k = 0; k < 4; k++) {
            int off = tid * 4 + k * 2048;
            float4 vv = *reinterpret_cast<const float4*>(g_v + off);
            #pragma unroll
            for (int r = 0; r < 4; r++) {
                float4 c = *reinterpret_cast<const float4*>(C0 + (size_t)r * NQ + off);
                ss[r] += (ex2f(fmaf(vv.x - c.x, K2, -rm2[r])) + ex2f(fmaf(vv.y - c.y, K2, -rm2[r])))
                       + (ex2f(fmaf(vv.z - c.z, K2, -rm2[r])) + ex2f(fmaf(vv.w - c.w, K2, -rm2[r])));
            }
        }
        #pragma unroll
        for (int r = 0; r < 4; r++) {
            float s = ss[r];
            #pragma unroll
            for (int off = 16; off; off >>= 1)
                s += __shfl_xor_sync(0xffffffffu, s, off);
            if (lane == 0) ssum[r][w] = s;
        }
        __syncthreads();
        if (tid < 4) {
            int i = i0 + tid;
            float S = ssum[tid][0];
            #pragma unroll
            for (int q = 1; q < 16; q++) S += ssum[tid][q];
            g_m[i]    = rm2[tid];
            g_sinv[i] = 1.0f / S;
        }
    }
}

// ---------------- out = softmax-weights(C) @ zq  (fused, split-K) ----------------
__global__ __launch_bounds__(256) void k_out(const float* __restrict__ B) {
    __shared__ float As[16][64];
    __shared__ float Bs[16][64];
    int tx = threadIdx.x & 15, ty = threadIdx.x >> 4;
    int m0 = blockIdx.y * 64;
    int n0 = blockIdx.x * 64;
    int kbase = blockIdx.z * (NQ / SPLITK);
    float acc[4][4] = {};
    for (int k0 = kbase; k0 < kbase + NQ / SPLITK; k0 += 16) {
        {
            int r  = threadIdx.x >> 2, k4 = threadIdx.x & 3;
            int row = m0 + r;
            float mi2 = g_m[row], si = g_sinv[row];
            float4 c  = *reinterpret_cast<const float4*>(g_C + (size_t)row * NQ + k0 + k4 * 4);
            float4 vv = *reinterpret_cast<const float4*>(g_v + k0 + k4 * 4);
            As[k4*4+0][r] = ex2f(fmaf(vv.x - c.x, K2, -mi2)) * si;
            As[k4*4+1][r] = ex2f(fmaf(vv.y - c.y, K2, -mi2)) * si;
            As[k4*4+2][r] = ex2f(fmaf(vv.z - c.z, K2, -mi2)) * si;
            As[k4*4+3][r] = ex2f(fmaf(vv.w - c.w, K2, -mi2)) * si;
            int kk = threadIdx.x >> 4, c4 = threadIdx.x & 15;
            float4 vb = *reinterpret_cast<const float4*>(B + (size_t)(k0 + kk) * DD + n0 + c4 * 4);
            *reinterpret_cast<float4*>(&Bs[kk][c4 * 4]) = vb;
        }
        __syncthreads();
        #pragma unroll
        for (int kk = 0; kk < 16; kk++) {
            float a[4], b[4];
            #pragma unroll
            for (int q = 0; q < 4; q++) { a[q] = As[kk][ty*4+q]; b[q] = Bs[kk][tx*4+q]; }
            #pragma unroll
            for (int ii = 0; ii < 4; ii++)
                #pragma unroll
                for (int jj = 0; jj < 4; jj++)
                    acc[ii][jj] = fmaf(a[ii], b[jj], acc[ii][jj]);
        }
        __syncthreads();
    }
    float* P = g_part + (size_t)blockIdx.z * NS * DD;
    #pragma unroll
    for (int ii = 0; ii < 4; ii++)
        #pragma unroll
        for (int jj = 0; jj < 4; jj++)
            P[(size_t)(m0 + ty*4 + ii) * DD + n0 + tx*4 + jj] = acc[ii][jj];
}

// ---------------- reduce split-K partials ----------------
__global__ void k_reduce(float* __restrict__ out) {
    int t = blockIdx.x * blockDim.x + threadIdx.x;
    float s = 0.0f;
    #pragma unroll
    for (int q = 0; q < SPLITK; q++) s += g_part[(size_t)q * NS * DD + t];
    out[t] = s;
}

// ---------------- copy z_query ----------------
__global__ void k_copy(const float* __restrict__ zq, float* __restrict__ out) {
    int t = blockIdx.x * blockDim.x + threadIdx.x;
    reinterpret_cast<float4*>(out)[t] = reinterpret_cast<const float4*>(zq)[t];
}

// ---------------- launch ----------------
extern "C" void kernel_launch(void* const* d_in, const int* in_sizes, int n_in,
                              void* d_out, int out_size) {
    const float* zs = (const float*)d_in[0];
    const float* zq = (const float*)d_in[1];
    if (n_in >= 2 && in_sizes[0] == NQ * DD) {
        const float* t = zs; zs = zq; zq = t;
    }
    float* out = (float*)d_out;

    k_init<<<(NQ + 255) / 256, 256>>>();
    k_norms<<<(NS + NQ) / 8, 256>>>(zs, zq);
    k_cost<<<dim3(NQ / 128, NS / 128), 256>>>(zs, zq);
    k_sink<<<GRIDB, TPB>>>();
    k_out<<<dim3(DD / 64, NS / 64, SPLITK), 256>>>(zq);
    k_reduce<<<(NS * DD) / 256, 256>>>(out);
    k_copy<<<(NQ * DD / 4) / 256, 256>>>(zq, out + NS * DD);
}

// round 8
// speedup vs baseline: 2.0290x; 1.0097x over previous
#include <cuda_runtime.h>
#include <math.h>
#include <stdint.h>

#define NS 1024
#define NQ 8192
#define DD 256
#define EPSR 0.05f
#define INV_EPS 20.0f
#define THRESHV 1e-3f
#define MAX_ITER 100
#define SPLITK 8
#define GRIDB 256
#define TPB 512

// log2-domain scale: INV_EPS * log2(e)
#define K2   28.853900817779268f
#define LN2  0.6931471805599453f
#define LOG_MU  (-6.93146156565f)
#define LOG_NU  (-9.01083143063f)

// ---------------- device scratch ----------------
__device__ float g_C[(size_t)NS * NQ];
__device__ float g_u[NS];
__device__ float g_v[NQ];
__device__ float g_rowerr[NS];
__device__ float g_mu[NS];      // per-row true max of (v-C), plain units
__device__ float g_mv[NQ];      // per-col true max of (u-C)*K2
__device__ float g_m[NS];       // final row shift (log2 domain) for k_out
__device__ float g_sinv[NS];
__device__ float g_x2[NS];
__device__ float g_y2[NQ];
__device__ float g_part[(size_t)SPLITK * NS * DD];
__device__ int   g_done;
__device__ int   g_dmax[2];     // max|du|*K2 bits, parity slots
__device__ int   g_dmaxv[2];    // max|dv|*K2 bits, parity slots
__device__ unsigned          g_arrive;
__device__ volatile unsigned g_gen;

// ---------------- MUFU helpers ----------------
__device__ __forceinline__ float ex2f(float x) {
    float r; asm("ex2.approx.f32 %0, %1;" : "=f"(r) : "f"(x)); return r;
}
__device__ __forceinline__ float lg2f(float x) {
    float r; asm("lg2.approx.f32 %0, %1;" : "=f"(r) : "f"(x)); return r;
}

// ---------------- software grid barrier ----------------
__device__ __forceinline__ void grid_barrier(unsigned target) {
    __syncthreads();
    if (threadIdx.x == 0) {
        __threadfence();
        unsigned prev = atomicAdd(&g_arrive, 1u);
        if (prev == GRIDB - 1) {
            g_arrive = 0;
            __threadfence();
            g_gen = target;
        } else {
            int spins = 0;
            while (g_gen != target) {
                if (++spins > 64) __nanosleep(32);
            }
            __threadfence();
        }
    }
    __syncthreads();
}

// ---------------- init ----------------
__global__ void k_init() {
    int t = blockIdx.x * blockDim.x + threadIdx.x;
    if (t < NS) { g_u[t] = 0.0f; g_mu[t] = 0.0f; }
    if (t < NQ) { g_v[t] = 0.0f; g_mv[t] = 0.0f; }
    if (t == 0) {
        g_done = 0; g_arrive = 0; g_gen = 0;
        g_dmax[0] = 0; g_dmax[1] = 0; g_dmaxv[0] = 0; g_dmaxv[1] = 0;
    }
}

// ---------------- squared norms ----------------
__global__ void k_norms(const float* __restrict__ zs, const float* __restrict__ zq) {
    int warp = (blockIdx.x * blockDim.x + threadIdx.x) >> 5;
    int lane = threadIdx.x & 31;
    if (warp >= NS + NQ) return;
    const float* row;
    float* out;
    if (warp < NS) { row = zs + (size_t)warp * DD;        out = g_x2 + warp; }
    else           { row = zq + (size_t)(warp - NS) * DD; out = g_y2 + (warp - NS); }
    float s = 0.0f;
    #pragma unroll
    for (int k = lane; k < DD; k += 32) { float v = row[k]; s = fmaf(v, v, s); }
    #pragma unroll
    for (int off = 16; off; off >>= 1) s += __shfl_down_sync(0xffffffffu, s, off);
    if (lane == 0) *out = s;
}

// ---------------- cost matrix: C = x2 + y2 - 2*A@B^T ----------------
__global__ __launch_bounds__(256) void k_cost(const float* __restrict__ A,
                                              const float* __restrict__ B) {
    __shared__ float As[16][128];
    __shared__ float Bs[16][128];
    int tx = threadIdx.x & 15, ty = threadIdx.x >> 4;
    int m0 = blockIdx.y * 128;
    int n0 = blockIdx.x * 128;
    float acc[8][8] = {};
    for (int k0 = 0; k0 < DD; k0 += 16) {
        #pragma unroll
        for (int t = 0; t < 2; t++) {
            int f  = threadIdx.x + t * 256;
            int r  = f >> 2, k4 = f & 3;
            float4 va = *reinterpret_cast<const float4*>(A + (size_t)(m0 + r) * DD + k0 + k4 * 4);
            As[k4*4+0][r] = va.x; As[k4*4+1][r] = va.y; As[k4*4+2][r] = va.z; As[k4*4+3][r] = va.w;
            float4 vb = *reinterpret_cast<const float4*>(B + (size_t)(n0 + r) * DD + k0 + k4 * 4);
            Bs[k4*4+0][r] = vb.x; Bs[k4*4+1][r] = vb.y; Bs[k4*4+2][r] = vb.z; Bs[k4*4+3][r] = vb.w;
        }
        __syncthreads();
        #pragma unroll
        for (int kk = 0; kk < 16; kk++) {
            float a[8], b[8];
            #pragma unroll
            for (int q = 0; q < 8; q++) { a[q] = As[kk][ty*8+q]; b[q] = Bs[kk][tx*8+q]; }
            #pragma unroll
            for (int ii = 0; ii < 8; ii++)
                #pragma unroll
                for (int jj = 0; jj < 8; jj++)
                    acc[ii][jj] = fmaf(a[ii], b[jj], acc[ii][jj]);
        }
        __syncthreads();
    }
    #pragma unroll
    for (int ii = 0; ii < 8; ii++) {
        int i = m0 + ty * 8 + ii;
        float x2 = g_x2[i];
        float* crow = g_C + (size_t)i * NQ + n0 + tx * 8;
        #pragma unroll
        for (int jj = 0; jj < 8; jj++) {
            int j = n0 + tx * 8 + jj;
            crow[jj] = x2 + g_y2[j] - 2.0f * acc[ii][jj];
        }
    }
}

// ---------------- persistent Sinkhorn loop + fused stats epilogue ----------------
__global__ __launch_bounds__(TPB, 2) void k_sink() {
    __shared__ float mrow[4][17];
    __shared__ float ssum[4][17];
    __shared__ float smv[64][33];     // v-phase per-rowgroup per-col max
    __shared__ float ssv[64][33];     // v-phase per-rowgroup per-col sum
    __shared__ float smM[32];         // v-phase broadcast max (two-pass)
    __shared__ float u2s[NS];
    __shared__ float sered[16];

    int tid  = threadIdx.x, bid = blockIdx.x;
    int lane = tid & 31,    w   = tid >> 5;     // 16 warps
    unsigned bargen = 0;
    bool done = false;
    int i0 = bid * 4;
    const float* C0 = g_C + (size_t)i0 * NQ;

    for (int it = 0; it < MAX_ITER; it++) {
        if (done) break;
        int par = it & 1;

        // ======== u phase: rows i0..i0+3 ========
        float dmv2 = __int_as_float(g_dmaxv[1 - par]);   // from prev v-phase
        bool onepass_u = (it > 0) && (dmv2 <= 20.0f);

        if (onepass_u) {
            float me2_0 = fmaf(g_mu[i0+0], K2, dmv2);
            float me2_1 = fmaf(g_mu[i0+1], K2, dmv2);
            float me2_2 = fmaf(g_mu[i0+2], K2, dmv2);
            float me2_3 = fmaf(g_mu[i0+3], K2, dmv2);
            float mx[4] = {-1e30f, -1e30f, -1e30f, -1e30f};
            float ss[4] = {0, 0, 0, 0};
            #pragma unroll
            for (int k = 0; k < 4; k++) {
                int off = tid * 4 + k * 2048;
                float4 vv = *reinterpret_cast<const float4*>(g_v + off);
                float4 c0 = *reinterpret_cast<const float4*>(C0 + off);
                float4 c1 = *reinterpret_cast<const float4*>(C0 + NQ + off);
                float4 c2 = *reinterpret_cast<const float4*>(C0 + 2 * NQ + off);
                float4 c3 = *reinterpret_cast<const float4*>(C0 + 3 * NQ + off);
                {
                    float a0 = vv.x - c0.x, a1 = vv.y - c0.y, a2 = vv.z - c0.z, a3 = vv.w - c0.w;
                    mx[0] = fmaxf(mx[0], fmaxf(fmaxf(a0, a1), fmaxf(a2, a3)));
                    ss[0] += (ex2f(fmaf(a0, K2, -me2_0)) + ex2f(fmaf(a1, K2, -me2_0)))
                           + (ex2f(fmaf(a2, K2, -me2_0)) + ex2f(fmaf(a3, K2, -me2_0)));
                }
                {
                    float a0 = vv.x - c1.x, a1 = vv.y - c1.y, a2 = vv.z - c1.z, a3 = vv.w - c1.w;
                    mx[1] = fmaxf(mx[1], fmaxf(fmaxf(a0, a1), fmaxf(a2, a3)));
                    ss[1] += (ex2f(fmaf(a0, K2, -me2_1)) + ex2f(fmaf(a1, K2, -me2_1)))
                           + (ex2f(fmaf(a2, K2, -me2_1)) + ex2f(fmaf(a3, K2, -me2_1)));
                }
                {
                    float a0 = vv.x - c2.x, a1 = vv.y - c2.y, a2 = vv.z - c2.z, a3 = vv.w - c2.w;
                    mx[2] = fmaxf(mx[2], fmaxf(fmaxf(a0, a1), fmaxf(a2, a3)));
                    ss[2] += (ex2f(fmaf(a0, K2, -me2_2)) + ex2f(fmaf(a1, K2, -me2_2)))
                           + (ex2f(fmaf(a2, K2, -me2_2)) + ex2f(fmaf(a3, K2, -me2_2)));
                }
                {
                    float a0 = vv.x - c3.x, a1 = vv.y - c3.y, a2 = vv.z - c3.z, a3 = vv.w - c3.w;
                    mx[3] = fmaxf(mx[3], fmaxf(fmaxf(a0, a1), fmaxf(a2, a3)));
                    ss[3] += (ex2f(fmaf(a0, K2, -me2_3)) + ex2f(fmaf(a1, K2, -me2_3)))
                           + (ex2f(fmaf(a2, K2, -me2_3)) + ex2f(fmaf(a3, K2, -me2_3)));
                }
            }
            #pragma unroll
            for (int r = 0; r < 4; r++) {
                float m = mx[r], s = ss[r];
                #pragma unroll
                for (int off = 16; off; off >>= 1) {
                    m = fmaxf(m, __shfl_xor_sync(0xffffffffu, m, off));
                    s += __shfl_xor_sync(0xffffffffu, s, off);
                }
                if (lane == 0) { mrow[r][w] = m; ssum[r][w] = s; }
            }
            __syncthreads();
            float delta2 = 0.0f;
            if (tid < 4) {
                int i = i0 + tid;
                float me2 = fmaf(g_mu[i], K2, dmv2);
                float mr = mrow[tid][0];
                float S  = ssum[tid][0];
                #pragma unroll
                for (int q = 1; q < 16; q++) { mr = fmaxf(mr, mrow[tid][q]); S += ssum[tid][q]; }
                float L    = LN2 * (me2 + lg2f(S));
                float unew = EPSR * (LOG_MU - L);
                float d    = fabsf(unew - g_u[i]);
                g_rowerr[i] = d;
                g_u[i]  = unew;
                g_mu[i] = mr;
                delta2 = d * K2;
            }
            if (w == 0) {
                #pragma unroll
                for (int off = 16; off; off >>= 1)
                    delta2 = fmaxf(delta2, __shfl_xor_sync(0xffffffffu, delta2, off));
                if (lane == 0) atomicMax(&g_dmax[par], __float_as_int(delta2));
            }
        } else {
            // exact two-pass streaming (early iterations only)
            float mx[4] = {-1e30f, -1e30f, -1e30f, -1e30f};
            #pragma unroll
            for (int k = 0; k < 4; k++) {
                int off = tid * 4 + k * 2048;
                float4 vv = *reinterpret_cast<const float4*>(g_v + off);
                #pragma unroll
                for (int r = 0; r < 4; r++) {
                    float4 c = *reinterpret_cast<const float4*>(C0 + (size_t)r * NQ + off);
                    mx[r] = fmaxf(mx[r], fmaxf(fmaxf(vv.x - c.x, vv.y - c.y),
                                               fmaxf(vv.z - c.z, vv.w - c.w)));
                }
            }
            #pragma unroll
            for (int r = 0; r < 4; r++) {
                float m = mx[r];
                #pragma unroll
                for (int off = 16; off; off >>= 1)
                    m = fmaxf(m, __shfl_xor_sync(0xffffffffu, m, off));
                if (lane == 0) mrow[r][w] = m;
            }
            __syncthreads();
            float rm2[4];
            #pragma unroll
            for (int r = 0; r < 4; r++) {
                float mr = mrow[r][0];
                #pragma unroll
                for (int q = 1; q < 16; q++) mr = fmaxf(mr, mrow[r][q]);
                rm2[r] = mr * K2;
                if (tid == r) g_mu[i0 + r] = mr;
            }
            float ss[4] = {0, 0, 0, 0};
            #pragma unroll
            for (int k = 0; k < 4; k++) {
                int off = tid * 4 + k * 2048;
                float4 vv = *reinterpret_cast<const float4*>(g_v + off);
                #pragma unroll
                for (int r = 0; r < 4; r++) {
                    float4 c = *reinterpret_cast<const float4*>(C0 + (size_t)r * NQ + off);
                    ss[r] += (ex2f(fmaf(vv.x - c.x, K2, -rm2[r])) + ex2f(fmaf(vv.y - c.y, K2, -rm2[r])))
                           + (ex2f(fmaf(vv.z - c.z, K2, -rm2[r])) + ex2f(fmaf(vv.w - c.w, K2, -rm2[r])));
                }
            }
            #pragma unroll
            for (int r = 0; r < 4; r++) {
                float s = ss[r];
                #pragma unroll
                for (int off = 16; off; off >>= 1)
                    s += __shfl_xor_sync(0xffffffffu, s, off);
                if (lane == 0) ssum[r][w] = s;
            }
            __syncthreads();
            float delta2 = 0.0f;
            if (tid < 4) {
                int i = i0 + tid;
                float S = ssum[tid][0];
                #pragma unroll
                for (int q = 1; q < 16; q++) S += ssum[tid][q];
                float L    = LN2 * (rm2[tid] + lg2f(S));
                float unew = EPSR * (LOG_MU - L);
                float d    = fabsf(unew - g_u[i]);
                g_rowerr[i] = d;
                g_u[i] = unew;
                delta2 = d * K2;
            }
            if (w == 0) {
                #pragma unroll
                for (int off = 16; off; off >>= 1)
                    delta2 = fmaxf(delta2, __shfl_xor_sync(0xffffffffu, delta2, off));
                if (lane == 0) atomicMax(&g_dmax[par], __float_as_int(delta2));
            }
        }

        grid_barrier(++bargen);

        // ======== v phase (float4): cols bid*32..+31; thread = (cg,rg) ========
        {
            u2s[tid]       = g_u[tid]       * K2;
            u2s[tid + TPB] = g_u[tid + TPB] * K2;
            if (bid == 0 && tid == 0) { g_dmax[1 - par] = 0; g_dmaxv[1 - par] = 0; }
            __syncthreads();

            float dmaxu2 = __int_as_float(g_dmax[par]);
            bool onepass = (it > 0) && (dmaxu2 <= 40.0f);

            int cg = tid & 7;          // column group: 4 consecutive cols
            int rg = tid >> 3;         // row group: 16 rows
            int jc = bid * 32 + cg * 4;
            const float* Cp = g_C + jc;
            int ib = rg * 16;

            if (onepass) {
                float4 mvp = *reinterpret_cast<const float4*>(g_mv + jc);
                float me0 = mvp.x + dmaxu2, me1 = mvp.y + dmaxu2;
                float me2 = mvp.z + dmaxu2, me3 = mvp.w + dmaxu2;
                float mx0 = -1e30f, mx1 = -1e30f, mx2 = -1e30f, mx3 = -1e30f;
                float s0 = 0, s1 = 0, s2 = 0, s3 = 0;
                #pragma unroll
                for (int ii = 0; ii < 16; ii++) {
                    int i = ib + ii;
                    float4 c = *reinterpret_cast<const float4*>(Cp + (size_t)i * NQ);
                    float u2 = u2s[i];
                    float a0 = fmaf(c.x, -K2, u2);
                    float a1 = fmaf(c.y, -K2, u2);
                    float a2 = fmaf(c.z, -K2, u2);
                    float a3 = fmaf(c.w, -K2, u2);
                    mx0 = fmaxf(mx0, a0); s0 += ex2f(a0 - me0);
                    mx1 = fmaxf(mx1, a1); s1 += ex2f(a1 - me1);
                    mx2 = fmaxf(mx2, a2); s2 += ex2f(a2 - me2);
                    mx3 = fmaxf(mx3, a3); s3 += ex2f(a3 - me3);
                }
                int cb = cg * 4;
                smv[rg][cb+0] = mx0; ssv[rg][cb+0] = s0;
                smv[rg][cb+1] = mx1; ssv[rg][cb+1] = s1;
                smv[rg][cb+2] = mx2; ssv[rg][cb+2] = s2;
                smv[rg][cb+3] = mx3; ssv[rg][cb+3] = s3;
                __syncthreads();
                if (tid < 32) {
                    int j = bid * 32 + tid;
                    float M = smv[0][tid], S = ssv[0][tid];
                    #pragma unroll
                    for (int q = 1; q < 64; q++) {
                        M = fmaxf(M, smv[q][tid]);
                        S += ssv[q][tid];
                    }
                    float m_est = g_mv[j] + dmaxu2;
                    g_mv[j] = M;
                    float vold = g_v[j];
                    float vnew = EPSR * (LOG_NU - LN2 * (m_est + lg2f(S)));
                    g_v[j] = vnew;
                    float dv2 = fabsf(vnew - vold) * K2;
                    #pragma unroll
                    for (int off = 16; off; off >>= 1)
                        dv2 = fmaxf(dv2, __shfl_xor_sync(0xffffffffu, dv2, off));
                    if (tid == 0) atomicMax(&g_dmaxv[par], __float_as_int(dv2));
                }
            } else {
                // pass 1: max
                float mx0 = -1e30f, mx1 = -1e30f, mx2 = -1e30f, mx3 = -1e30f;
                #pragma unroll
                for (int ii = 0; ii < 16; ii++) {
                    int i = ib + ii;
                    float4 c = *reinterpret_cast<const float4*>(Cp + (size_t)i * NQ);
                    float u2 = u2s[i];
                    mx0 = fmaxf(mx0, fmaf(c.x, -K2, u2));
                    mx1 = fmaxf(mx1, fmaf(c.y, -K2, u2));
                    mx2 = fmaxf(mx2, fmaf(c.z, -K2, u2));
                    mx3 = fmaxf(mx3, fmaf(c.w, -K2, u2));
                }
                int cb = cg * 4;
                smv[rg][cb+0] = mx0; smv[rg][cb+1] = mx1;
                smv[rg][cb+2] = mx2; smv[rg][cb+3] = mx3;
                __syncthreads();
                if (tid < 32) {
                    float M = smv[0][tid];
                    #pragma unroll
                    for (int q = 1; q < 64; q++) M = fmaxf(M, smv[q][tid]);
                    smM[tid] = M;
                }
                __syncthreads();
                float M0 = smM[cb+0], M1 = smM[cb+1], M2 = smM[cb+2], M3 = smM[cb+3];
                float s0 = 0, s1 = 0, s2 = 0, s3 = 0;
                #pragma unroll
                for (int ii = 0; ii < 16; ii++) {
                    int i = ib + ii;
                    float4 c = *reinterpret_cast<const float4*>(Cp + (size_t)i * NQ);
                    float u2 = u2s[i];
                    s0 += ex2f(fmaf(c.x, -K2, u2) - M0);
                    s1 += ex2f(fmaf(c.y, -K2, u2) - M1);
                    s2 += ex2f(fmaf(c.z, -K2, u2) - M2);
                    s3 += ex2f(fmaf(c.w, -K2, u2) - M3);
                }
                ssv[rg][cb+0] = s0; ssv[rg][cb+1] = s1;
                ssv[rg][cb+2] = s2; ssv[rg][cb+3] = s3;
                __syncthreads();
                if (tid < 32) {
                    int j = bid * 32 + tid;
                    float S = ssv[0][tid];
                    #pragma unroll
                    for (int q = 1; q < 64; q++) S += ssv[q][tid];
                    float M = smM[tid];
                    g_mv[j] = M;
                    float vold = g_v[j];
                    float vnew = EPSR * (LOG_NU - LN2 * (M + lg2f(S)));
                    g_v[j] = vnew;
                    float dv2 = fabsf(vnew - vold) * K2;
                    #pragma unroll
                    for (int off = 16; off; off >>= 1)
                        dv2 = fmaxf(dv2, __shfl_xor_sync(0xffffffffu, dv2, off));
                    if (tid == 0) atomicMax(&g_dmaxv[par], __float_as_int(dv2));
                }
            }

            // block 0: convergence check
            if (bid == 0) {
                float e = g_rowerr[tid] + g_rowerr[tid + TPB];
                #pragma unroll
                for (int off = 16; off; off >>= 1)
                    e += __shfl_down_sync(0xffffffffu, e, off);
                if (lane == 0) sered[w] = e;
                __syncthreads();
                if (tid == 0) {
                    float E = 0;
                    #pragma unroll
                    for (int q = 0; q < 16; q++) E += sered[q];
                    if (E < THRESHV) g_done = 1;
                }
            }
        }

        grid_barrier(++bargen);
        done = (*(volatile int*)&g_done) != 0;
    }

    // ======== fused stats epilogue: exact two-pass with FINAL v ========
    {
        float mx[4] = {-1e30f, -1e30f, -1e30f, -1e30f};
        #pragma unroll
        for (int k = 0; k < 4; k++) {
            int off = tid * 4 + k * 2048;
            float4 vv = *reinterpret_cast<const float4*>(g_v + off);
            #pragma unroll
            for (int r = 0; r < 4; r++) {
                float4 c = *reinterpret_cast<const float4*>(C0 + (size_t)r * NQ + off);
                mx[r] = fmaxf(mx[r], fmaxf(fmaxf(vv.x - c.x, vv.y - c.y),
                                           fmaxf(vv.z - c.z, vv.w - c.w)));
            }
        }
        #pragma unroll
        for (int r = 0; r < 4; r++) {
            float m = mx[r];
            #pragma unroll
            for (int off = 16; off; off >>= 1)
                m = fmaxf(m, __shfl_xor_sync(0xffffffffu, m, off));
            if (lane == 0) mrow[r][w] = m;
        }
        __syncthreads();
        float rm2[4];
        #pragma unroll
        for (int r = 0; r < 4; r++) {
            float mr = mrow[r][0];
            #pragma unroll
            for (int q = 1; q < 16; q++) mr = fmaxf(mr, mrow[r][q]);
            rm2[r] = mr * K2;
        }
        float ss[4] = {0, 0, 0, 0};
        #pragma unroll
        for (int k = 0; k < 4; k++) {
            int off = tid * 4 + k * 2048;
            float4 vv = *reinterpret_cast<const float4*>(g_v + off);
            #pragma unroll
            for (int r = 0; r < 4; r++) {
                float4 c = *reinterpret_cast<const float4*>(C0 + (size_t)r * NQ + off);
                ss[r] += (ex2f(fmaf(vv.x - c.x, K2, -rm2[r])) + ex2f(fmaf(vv.y - c.y, K2, -rm2[r])))
                       + (ex2f(fmaf(vv.z - c.z, K2, -rm2[r])) + ex2f(fmaf(vv.w - c.w, K2, -rm2[r])));
            }
        }
        #pragma unroll
        for (int r = 0; r < 4; r++) {
            float s = ss[r];
            #pragma unroll
            for (int off = 16; off; off >>= 1)
                s += __shfl_xor_sync(0xffffffffu, s, off);
            if (lane == 0) ssum[r][w] = s;
        }
        __syncthreads();
        if (tid < 4) {
            int i = i0 + tid;
            float S = ssum[tid][0];
            #pragma unroll
            for (int q = 1; q < 16; q++) S += ssum[tid][q];
            g_m[i]    = rm2[tid];
            g_sinv[i] = 1.0f / S;
        }
    }
}

// ---------------- out = softmax-weights(C) @ zq  (fused, split-K) ----------------
__global__ __launch_bounds__(256) void k_out(const float* __restrict__ B) {
    __shared__ float As[16][64];
    __shared__ float Bs[16][64];
    int tx = threadIdx.x & 15, ty = threadIdx.x >> 4;
    int m0 = blockIdx.y * 64;
    int n0 = blockIdx.x * 64;
    int kbase = blockIdx.z * (NQ / SPLITK);
    float acc[4][4] = {};
    for (int k0 = kbase; k0 < kbase + NQ / SPLITK; k0 += 16) {
        {
            int r  = threadIdx.x >> 2, k4 = threadIdx.x & 3;
            int row = m0 + r;
            float mi2 = g_m[row], si = g_sinv[row];
            float4 c  = *reinterpret_cast<const float4*>(g_C + (size_t)row * NQ + k0 + k4 * 4);
            float4 vv = *reinterpret_cast<const float4*>(g_v + k0 + k4 * 4);
            As[k4*4+0][r] = ex2f(fmaf(vv.x - c.x, K2, -mi2)) * si;
            As[k4*4+1][r] = ex2f(fmaf(vv.y - c.y, K2, -mi2)) * si;
            As[k4*4+2][r] = ex2f(fmaf(vv.z - c.z, K2, -mi2)) * si;
            As[k4*4+3][r] = ex2f(fmaf(vv.w - c.w, K2, -mi2)) * si;
            int kk = threadIdx.x >> 4, c4 = threadIdx.x & 15;
            float4 vb = *reinterpret_cast<const float4*>(B + (size_t)(k0 + kk) * DD + n0 + c4 * 4);
            *reinterpret_cast<float4*>(&Bs[kk][c4 * 4]) = vb;
        }
        __syncthreads();
        #pragma unroll
        for (int kk = 0; kk < 16; kk++) {
            float a[4], b[4];
            #pragma unroll
            for (int q = 0; q < 4; q++) { a[q] = As[kk][ty*4+q]; b[q] = Bs[kk][tx*4+q]; }
            #pragma unroll
            for (int ii = 0; ii < 4; ii++)
                #pragma unroll
                for (int jj = 0; jj < 4; jj++)
                    acc[ii][jj] = fmaf(a[ii], b[jj], acc[ii][jj]);
        }
        __syncthreads();
    }
    float* P = g_part + (size_t)blockIdx.z * NS * DD;
    #pragma unroll
    for (int ii = 0; ii < 4; ii++)
        #pragma unroll
        for (int jj = 0; jj < 4; jj++)
            P[(size_t)(m0 + ty*4 + ii) * DD + n0 + tx*4 + jj] = acc[ii][jj];
}

// ---------------- reduce split-K partials ----------------
__global__ void k_reduce(float* __restrict__ out) {
    int t = blockIdx.x * blockDim.x + threadIdx.x;
    float s = 0.0f;
    #pragma unroll
    for (int q = 0; q < SPLITK; q++) s += g_part[(size_t)q * NS * DD + t];
    out[t] = s;
}

// ---------------- copy z_query ----------------
__global__ void k_copy(const float* __restrict__ zq, float* __restrict__ out) {
    int t = blockIdx.x * blockDim.x + threadIdx.x;
    reinterpret_cast<float4*>(out)[t] = reinterpret_cast<const float4*>(zq)[t];
}

// ---------------- launch ----------------
extern "C" void kernel_launch(void* const* d_in, const int* in_sizes, int n_in,
                              void* d_out, int out_size) {
    const float* zs = (const float*)d_in[0];
    const float* zq = (const float*)d_in[1];
    if (n_in >= 2 && in_sizes[0] == NQ * DD) {
        const float* t = zs; zs = zq; zq = t;
    }
    float* out = (float*)d_out;

    k_init<<<(NQ + 255) / 256, 256>>>();
    k_norms<<<(NS + NQ) / 8, 256>>>(zs, zq);
    k_cost<<<dim3(NQ / 128, NS / 128), 256>>>(zs, zq);
    k_sink<<<GRIDB, TPB>>>();
    k_out<<<dim3(DD / 64, NS / 64, SPLITK), 256>>>(zq);
    k_reduce<<<(NS * DD) / 256, 256>>>(out);
    k_copy<<<(NQ * DD / 4) / 256, 256>>>(zq, out + NS * DD);
}

// round 9
// speedup vs baseline: 2.1190x; 1.0444x over previous
#include <cuda_runtime.h>
#include <math.h>
#include <stdint.h>

#define NS 1024
#define NQ 8192
#define DD 256
#define EPSR 0.05f
#define INV_EPS 20.0f
#define THRESHV 1e-3f
#define MAX_ITER 100
#define SPLITK 16
#define GRIDB 256
#define TPB 512

// log2-domain scale: INV_EPS * log2(e)
#define K2   28.853900817779268f
#define LN2  0.6931471805599453f
#define LOG_MU  (-6.93146156565f)
#define LOG_NU  (-9.01083143063f)

// ---------------- device scratch ----------------
__device__ float g_C[(size_t)NS * NQ];
__device__ float g_u[NS];
__device__ float g_v[NQ];
__device__ float g_rowerr[NS];
__device__ float g_mu[NS];
__device__ float g_mv[NQ];
__device__ float g_m[NS];
__device__ float g_sinv[NS];
__device__ float g_x2[NS];
__device__ float g_y2[NQ];
__device__ float g_part[(size_t)SPLITK * NS * DD];
__device__ int   g_done;
__device__ int   g_dmax[2];
__device__ int   g_dmaxv[2];
__device__ unsigned          g_arrive;
__device__ volatile unsigned g_gen;

// ---------------- MUFU / tf32 helpers ----------------
__device__ __forceinline__ float ex2f(float x) {
    float r; asm("ex2.approx.f32 %0, %1;" : "=f"(r) : "f"(x)); return r;
}
__device__ __forceinline__ float lg2f(float x) {
    float r; asm("lg2.approx.f32 %0, %1;" : "=f"(r) : "f"(x)); return r;
}
__device__ __forceinline__ uint32_t tf32r(float x) {
    uint32_t u; asm("cvt.rna.tf32.f32 %0, %1;" : "=r"(u) : "f"(x)); return u;
}
__device__ __forceinline__ void mma_tf32(float* c,
    uint32_t a0, uint32_t a1, uint32_t a2, uint32_t a3,
    uint32_t b0, uint32_t b1) {
    asm volatile(
        "mma.sync.aligned.m16n8k8.row.col.f32.tf32.tf32.f32 "
        "{%0,%1,%2,%3},{%4,%5,%6,%7},{%8,%9},{%0,%1,%2,%3};\n"
        : "+f"(c[0]), "+f"(c[1]), "+f"(c[2]), "+f"(c[3])
        : "r"(a0), "r"(a1), "r"(a2), "r"(a3), "r"(b0), "r"(b1));
}

// ---------------- software grid barrier ----------------
__device__ __forceinline__ void grid_barrier(unsigned target) {
    __syncthreads();
    if (threadIdx.x == 0) {
        __threadfence();
        unsigned prev = atomicAdd(&g_arrive, 1u);
        if (prev == GRIDB - 1) {
            g_arrive = 0;
            __threadfence();
            g_gen = target;
        } else {
            int spins = 0;
            while (g_gen != target) {
                if (++spins > 64) __nanosleep(32);
            }
            __threadfence();
        }
    }
    __syncthreads();
}

// ---------------- init ----------------
__global__ void k_init() {
    int t = blockIdx.x * blockDim.x + threadIdx.x;
    if (t < NS) { g_u[t] = 0.0f; g_mu[t] = 0.0f; }
    if (t < NQ) { g_v[t] = 0.0f; g_mv[t] = 0.0f; }
    if (t == 0) {
        g_done = 0; g_arrive = 0; g_gen = 0;
        g_dmax[0] = 0; g_dmax[1] = 0; g_dmaxv[0] = 0; g_dmaxv[1] = 0;
    }
}

// ---------------- squared norms ----------------
__global__ void k_norms(const float* __restrict__ zs, const float* __restrict__ zq) {
    int warp = (blockIdx.x * blockDim.x + threadIdx.x) >> 5;
    int lane = threadIdx.x & 31;
    if (warp >= NS + NQ) return;
    const float* row;
    float* out;
    if (warp < NS) { row = zs + (size_t)warp * DD;        out = g_x2 + warp; }
    else           { row = zq + (size_t)(warp - NS) * DD; out = g_y2 + (warp - NS); }
    float s = 0.0f;
    #pragma unroll
    for (int k = lane; k < DD; k += 32) { float v = row[k]; s = fmaf(v, v, s); }
    #pragma unroll
    for (int off = 16; off; off >>= 1) s += __shfl_down_sync(0xffffffffu, s, off);
    if (lane == 0) *out = s;
}

// ---------------- cost matrix via tf32 mma (3-product split) ----------------
// C = x2 + y2 - 2*A@B^T, tile 128x128, kc=16 per stage
#define APAD 20
__global__ __launch_bounds__(256) void k_cost(const float* __restrict__ A,
                                              const float* __restrict__ B) {
    __shared__ float Ah[128][APAD], Al[128][APAD];
    __shared__ float Bh[128][APAD], Bl[128][APAD];
    int tid = threadIdx.x;
    int lane = tid & 31, wid = tid >> 5;
    int warp_m = (wid & 3) * 32, warp_n = (wid >> 2) * 64;
    int m0 = blockIdx.y * 128, n0 = blockIdx.x * 128;
    int gid = lane >> 2, tig = lane & 3;

    float acc[2][8][4];
    #pragma unroll
    for (int mi = 0; mi < 2; mi++)
        #pragma unroll
        for (int ni = 0; ni < 8; ni++)
            #pragma unroll
            for (int q = 0; q < 4; q++) acc[mi][ni][q] = 0.0f;

    for (int kk0 = 0; kk0 < DD; kk0 += 16) {
        // load + split tiles
        #pragma unroll
        for (int q = 0; q < 2; q++) {
            int i = tid + q * 256;         // 0..511
            int row = i >> 2, f4 = i & 3;
            float4 a = *reinterpret_cast<const float4*>(A + (size_t)(m0 + row) * DD + kk0 + f4 * 4);
            float4 b = *reinterpret_cast<const float4*>(B + (size_t)(n0 + row) * DD + kk0 + f4 * 4);
            float4 hx, lx;
            hx.x = __uint_as_float(tf32r(a.x)); lx.x = __uint_as_float(tf32r(a.x - hx.x));
            hx.y = __uint_as_float(tf32r(a.y)); lx.y = __uint_as_float(tf32r(a.y - hx.y));
            hx.z = __uint_as_float(tf32r(a.z)); lx.z = __uint_as_float(tf32r(a.z - hx.z));
            hx.w = __uint_as_float(tf32r(a.w)); lx.w = __uint_as_float(tf32r(a.w - hx.w));
            *reinterpret_cast<float4*>(&Ah[row][f4 * 4]) = hx;
            *reinterpret_cast<float4*>(&Al[row][f4 * 4]) = lx;
            hx.x = __uint_as_float(tf32r(b.x)); lx.x = __uint_as_float(tf32r(b.x - hx.x));
            hx.y = __uint_as_float(tf32r(b.y)); lx.y = __uint_as_float(tf32r(b.y - hx.y));
            hx.z = __uint_as_float(tf32r(b.z)); lx.z = __uint_as_float(tf32r(b.z - hx.z));
            hx.w = __uint_as_float(tf32r(b.w)); lx.w = __uint_as_float(tf32r(b.w - hx.w));
            *reinterpret_cast<float4*>(&Bh[row][f4 * 4]) = hx;
            *reinterpret_cast<float4*>(&Bl[row][f4 * 4]) = lx;
        }
        __syncthreads();
        #pragma unroll
        for (int k8 = 0; k8 < 2; k8++) {
            int kc = k8 * 8 + tig;
            uint32_t ah[2][4], al[2][4];
            #pragma unroll
            for (int mi = 0; mi < 2; mi++) {
                int rb = warp_m + mi * 16 + gid;
                ah[mi][0] = __float_as_uint(Ah[rb][kc]);
                ah[mi][1] = __float_as_uint(Ah[rb + 8][kc]);
                ah[mi][2] = __float_as_uint(Ah[rb][kc + 4]);
                ah[mi][3] = __float_as_uint(Ah[rb + 8][kc + 4]);
                al[mi][0] = __float_as_uint(Al[rb][kc]);
                al[mi][1] = __float_as_uint(Al[rb + 8][kc]);
                al[mi][2] = __float_as_uint(Al[rb][kc + 4]);
                al[mi][3] = __float_as_uint(Al[rb + 8][kc + 4]);
            }
            #pragma unroll
            for (int ni = 0; ni < 8; ni++) {
                int nb = warp_n + ni * 8 + gid;
                uint32_t bh0 = __float_as_uint(Bh[nb][kc]);
                uint32_t bh1 = __float_as_uint(Bh[nb][kc + 4]);
                uint32_t bl0 = __float_as_uint(Bl[nb][kc]);
                uint32_t bl1 = __float_as_uint(Bl[nb][kc + 4]);
                #pragma unroll
                for (int mi = 0; mi < 2; mi++) {
                    mma_tf32(acc[mi][ni], ah[mi][0], ah[mi][1], ah[mi][2], ah[mi][3], bh0, bh1);
                    mma_tf32(acc[mi][ni], ah[mi][0], ah[mi][1], ah[mi][2], ah[mi][3], bl0, bl1);
                    mma_tf32(acc[mi][ni], al[mi][0], al[mi][1], al[mi][2], al[mi][3], bh0, bh1);
                }
            }
        }
        __syncthreads();
    }
    // epilogue: C = x2 + y2 - 2*acc
    #pragma unroll
    for (int mi = 0; mi < 2; mi++) {
        int r0 = m0 + warp_m + mi * 16 + gid;
        float x2a = g_x2[r0], x2b = g_x2[r0 + 8];
        #pragma unroll
        for (int ni = 0; ni < 8; ni++) {
            int c0 = n0 + warp_n + ni * 8 + 2 * tig;
            float y20 = g_y2[c0], y21 = g_y2[c0 + 1];
            float2 w0 = { x2a + y20 - 2.0f * acc[mi][ni][0],
                          x2a + y21 - 2.0f * acc[mi][ni][1] };
            float2 w1 = { x2b + y20 - 2.0f * acc[mi][ni][2],
                          x2b + y21 - 2.0f * acc[mi][ni][3] };
            *reinterpret_cast<float2*>(g_C + (size_t)r0 * NQ + c0) = w0;
            *reinterpret_cast<float2*>(g_C + (size_t)(r0 + 8) * NQ + c0) = w1;
        }
    }
}

// ---------------- persistent Sinkhorn loop + fused stats epilogue ----------------
__global__ __launch_bounds__(TPB, 2) void k_sink() {
    __shared__ float mrow[4][17];
    __shared__ float ssum[4][17];
    __shared__ float smv[64][33];
    __shared__ float ssv[64][33];
    __shared__ float smM[32];
    __shared__ float u2s[NS];
    __shared__ float sered[16];

    int tid  = threadIdx.x, bid = blockIdx.x;
    int lane = tid & 31,    w   = tid >> 5;
    unsigned bargen = 0;
    bool done = false;
    int i0 = bid * 4;
    const float* C0 = g_C + (size_t)i0 * NQ;

    for (int it = 0; it < MAX_ITER; it++) {
        if (done) break;
        int par = it & 1;

        float dmv2 = __int_as_float(g_dmaxv[1 - par]);
        bool onepass_u = (it > 0) && (dmv2 <= 20.0f);

        if (onepass_u) {
            float me2_0 = fmaf(g_mu[i0+0], K2, dmv2);
            float me2_1 = fmaf(g_mu[i0+1], K2, dmv2);
            float me2_2 = fmaf(g_mu[i0+2], K2, dmv2);
            float me2_3 = fmaf(g_mu[i0+3], K2, dmv2);
            float mx[4] = {-1e30f, -1e30f, -1e30f, -1e30f};
            float ss[4] = {0, 0, 0, 0};
            #pragma unroll
            for (int k = 0; k < 4; k++) {
                int off = tid * 4 + k * 2048;
                float4 vv = *reinterpret_cast<const float4*>(g_v + off);
                float4 c0 = *reinterpret_cast<const float4*>(C0 + off);
                float4 c1 = *reinterpret_cast<const float4*>(C0 + NQ + off);
                float4 c2 = *reinterpret_cast<const float4*>(C0 + 2 * NQ + off);
                float4 c3 = *reinterpret_cast<const float4*>(C0 + 3 * NQ + off);
                {
                    float a0 = vv.x - c0.x, a1 = vv.y - c0.y, a2 = vv.z - c0.z, a3 = vv.w - c0.w;
                    mx[0] = fmaxf(mx[0], fmaxf(fmaxf(a0, a1), fmaxf(a2, a3)));
                    ss[0] += (ex2f(fmaf(a0, K2, -me2_0)) + ex2f(fmaf(a1, K2, -me2_0)))
                           + (ex2f(fmaf(a2, K2, -me2_0)) + ex2f(fmaf(a3, K2, -me2_0)));
                }
                {
                    float a0 = vv.x - c1.x, a1 = vv.y - c1.y, a2 = vv.z - c1.z, a3 = vv.w - c1.w;
                    mx[1] = fmaxf(mx[1], fmaxf(fmaxf(a0, a1), fmaxf(a2, a3)));
                    ss[1] += (ex2f(fmaf(a0, K2, -me2_1)) + ex2f(fmaf(a1, K2, -me2_1)))
                           + (ex2f(fmaf(a2, K2, -me2_1)) + ex2f(fmaf(a3, K2, -me2_1)));
                }
                {
                    float a0 = vv.x - c2.x, a1 = vv.y - c2.y, a2 = vv.z - c2.z, a3 = vv.w - c2.w;
                    mx[2] = fmaxf(mx[2], fmaxf(fmaxf(a0, a1), fmaxf(a2, a3)));
                    ss[2] += (ex2f(fmaf(a0, K2, -me2_2)) + ex2f(fmaf(a1, K2, -me2_2)))
                           + (ex2f(fmaf(a2, K2, -me2_2)) + ex2f(fmaf(a3, K2, -me2_2)));
                }
                {
                    float a0 = vv.x - c3.x, a1 = vv.y - c3.y, a2 = vv.z - c3.z, a3 = vv.w - c3.w;
                    mx[3] = fmaxf(mx[3], fmaxf(fmaxf(a0, a1), fmaxf(a2, a3)));
                    ss[3] += (ex2f(fmaf(a0, K2, -me2_3)) + ex2f(fmaf(a1, K2, -me2_3)))
                           + (ex2f(fmaf(a2, K2, -me2_3)) + ex2f(fmaf(a3, K2, -me2_3)));
                }
            }
            #pragma unroll
            for (int r = 0; r < 4; r++) {
                float m = mx[r], s = ss[r];
                #pragma unroll
                for (int off = 16; off; off >>= 1) {
                    m = fmaxf(m, __shfl_xor_sync(0xffffffffu, m, off));
                    s += __shfl_xor_sync(0xffffffffu, s, off);
                }
                if (lane == 0) { mrow[r][w] = m; ssum[r][w] = s; }
            }
            __syncthreads();
            float delta2 = 0.0f;
            if (tid < 4) {
                int i = i0 + tid;
                float me2 = fmaf(g_mu[i], K2, dmv2);
                float mr = mrow[tid][0];
                float S  = ssum[tid][0];
                #pragma unroll
                for (int q = 1; q < 16; q++) { mr = fmaxf(mr, mrow[tid][q]); S += ssum[tid][q]; }
                float L    = LN2 * (me2 + lg2f(S));
                float unew = EPSR * (LOG_MU - L);
                float d    = fabsf(unew - g_u[i]);
                g_rowerr[i] = d;
                g_u[i]  = unew;
                g_mu[i] = mr;
                delta2 = d * K2;
            }
            if (w == 0) {
                #pragma unroll
                for (int off = 16; off; off >>= 1)
                    delta2 = fmaxf(delta2, __shfl_xor_sync(0xffffffffu, delta2, off));
                if (lane == 0) atomicMax(&g_dmax[par], __float_as_int(delta2));
            }
        } else {
            float mx[4] = {-1e30f, -1e30f, -1e30f, -1e30f};
            #pragma unroll
            for (int k = 0; k < 4; k++) {
                int off = tid * 4 + k * 2048;
                float4 vv = *reinterpret_cast<const float4*>(g_v + off);
                #pragma unroll
                for (int r = 0; r < 4; r++) {
                    float4 c = *reinterpret_cast<const float4*>(C0 + (size_t)r * NQ + off);
                    mx[r] = fmaxf(mx[r], fmaxf(fmaxf(vv.x - c.x, vv.y - c.y),
                                               fmaxf(vv.z - c.z, vv.w - c.w)));
                }
            }
            #pragma unroll
            for (int r = 0; r < 4; r++) {
                float m = mx[r];
                #pragma unroll
                for (int off = 16; off; off >>= 1)
                    m = fmaxf(m, __shfl_xor_sync(0xffffffffu, m, off));
                if (lane == 0) mrow[r][w] = m;
            }
            __syncthreads();
            float rm2[4];
            #pragma unroll
            for (int r = 0; r < 4; r++) {
                float mr = mrow[r][0];
                #pragma unroll
                for (int q = 1; q < 16; q++) mr = fmaxf(mr, mrow[r][q]);
                rm2[r] = mr * K2;
                if (tid == r) g_mu[i0 + r] = mr;
            }
            float ss[4] = {0, 0, 0, 0};
            #pragma unroll
            for (int k = 0; k < 4; k++) {
                int off = tid * 4 + k * 2048;
                float4 vv = *reinterpret_cast<const float4*>(g_v + off);
                #pragma unroll
                for (int r = 0; r < 4; r++) {
                    float4 c = *reinterpret_cast<const float4*>(C0 + (size_t)r * NQ + off);
                    ss[r] += (ex2f(fmaf(vv.x - c.x, K2, -rm2[r])) + ex2f(fmaf(vv.y - c.y, K2, -rm2[r])))
                           + (ex2f(fmaf(vv.z - c.z, K2, -rm2[r])) + ex2f(fmaf(vv.w - c.w, K2, -rm2[r])));
                }
            }
            #pragma unroll
            for (int r = 0; r < 4; r++) {
                float s = ss[r];
                #pragma unroll
                for (int off = 16; off; off >>= 1)
                    s += __shfl_xor_sync(0xffffffffu, s, off);
                if (lane == 0) ssum[r][w] = s;
            }
            __syncthreads();
            float delta2 = 0.0f;
            if (tid < 4) {
                int i = i0 + tid;
                float S = ssum[tid][0];
                #pragma unroll
                for (int q = 1; q < 16; q++) S += ssum[tid][q];
                float L    = LN2 * (rm2[tid] + lg2f(S));
                float unew = EPSR * (LOG_MU - L);
                float d    = fabsf(unew - g_u[i]);
                g_rowerr[i] = d;
                g_u[i] = unew;
                delta2 = d * K2;
            }
            if (w == 0) {
                #pragma unroll
                for (int off = 16; off; off >>= 1)
                    delta2 = fmaxf(delta2, __shfl_xor_sync(0xffffffffu, delta2, off));
                if (lane == 0) atomicMax(&g_dmax[par], __float_as_int(delta2));
            }
        }

        grid_barrier(++bargen);

        {
            u2s[tid]       = g_u[tid]       * K2;
            u2s[tid + TPB] = g_u[tid + TPB] * K2;
            if (bid == 0 && tid == 0) { g_dmax[1 - par] = 0; g_dmaxv[1 - par] = 0; }
            __syncthreads();

            float dmaxu2 = __int_as_float(g_dmax[par]);
            bool onepass = (it > 0) && (dmaxu2 <= 40.0f);

            int cg = tid & 7;
            int rg = tid >> 3;
            int jc = bid * 32 + cg * 4;
            const float* Cp = g_C + jc;
            int ib = rg * 16;

            if (onepass) {
                float4 mvp = *reinterpret_cast<const float4*>(g_mv + jc);
                float me0 = mvp.x + dmaxu2, me1 = mvp.y + dmaxu2;
                float me2 = mvp.z + dmaxu2, me3 = mvp.w + dmaxu2;
                float mx0 = -1e30f, mx1 = -1e30f, mx2 = -1e30f, mx3 = -1e30f;
                float s0 = 0, s1 = 0, s2 = 0, s3 = 0;
                #pragma unroll
                for (int ii = 0; ii < 16; ii++) {
                    int i = ib + ii;
                    float4 c = *reinterpret_cast<const float4*>(Cp + (size_t)i * NQ);
                    float u2 = u2s[i];
                    float a0 = fmaf(c.x, -K2, u2);
                    float a1 = fmaf(c.y, -K2, u2);
                    float a2 = fmaf(c.z, -K2, u2);
                    float a3 = fmaf(c.w, -K2, u2);
                    mx0 = fmaxf(mx0, a0); s0 += ex2f(a0 - me0);
                    mx1 = fmaxf(mx1, a1); s1 += ex2f(a1 - me1);
                    mx2 = fmaxf(mx2, a2); s2 += ex2f(a2 - me2);
                    mx3 = fmaxf(mx3, a3); s3 += ex2f(a3 - me3);
                }
                int cb = cg * 4;
                smv[rg][cb+0] = mx0; ssv[rg][cb+0] = s0;
                smv[rg][cb+1] = mx1; ssv[rg][cb+1] = s1;
                smv[rg][cb+2] = mx2; ssv[rg][cb+2] = s2;
                smv[rg][cb+3] = mx3; ssv[rg][cb+3] = s3;
                __syncthreads();
                if (tid < 32) {
                    int j = bid * 32 + tid;
                    float M = smv[0][tid], S = ssv[0][tid];
                    #pragma unroll
                    for (int q = 1; q < 64; q++) {
                        M = fmaxf(M, smv[q][tid]);
                        S += ssv[q][tid];
                    }
                    float m_est = g_mv[j] + dmaxu2;
                    g_mv[j] = M;
                    float vold = g_v[j];
                    float vnew = EPSR * (LOG_NU - LN2 * (m_est + lg2f(S)));
                    g_v[j] = vnew;
                    float dv2 = fabsf(vnew - vold) * K2;
                    #pragma unroll
                    for (int off = 16; off; off >>= 1)
                        dv2 = fmaxf(dv2, __shfl_xor_sync(0xffffffffu, dv2, off));
                    if (tid == 0) atomicMax(&g_dmaxv[par], __float_as_int(dv2));
                }
            } else {
                float mx0 = -1e30f, mx1 = -1e30f, mx2 = -1e30f, mx3 = -1e30f;
                #pragma unroll
                for (int ii = 0; ii < 16; ii++) {
                    int i = ib + ii;
                    float4 c = *reinterpret_cast<const float4*>(Cp + (size_t)i * NQ);
                    float u2 = u2s[i];
                    mx0 = fmaxf(mx0, fmaf(c.x, -K2, u2));
                    mx1 = fmaxf(mx1, fmaf(c.y, -K2, u2));
                    mx2 = fmaxf(mx2, fmaf(c.z, -K2, u2));
                    mx3 = fmaxf(mx3, fmaf(c.w, -K2, u2));
                }
                int cb = cg * 4;
                smv[rg][cb+0] = mx0; smv[rg][cb+1] = mx1;
                smv[rg][cb+2] = mx2; smv[rg][cb+3] = mx3;
                __syncthreads();
                if (tid < 32) {
                    float M = smv[0][tid];
                    #pragma unroll
                    for (int q = 1; q < 64; q++) M = fmaxf(M, smv[q][tid]);
                    smM[tid] = M;
                }
                __syncthreads();
                float M0 = smM[cb+0], M1 = smM[cb+1], M2 = smM[cb+2], M3 = smM[cb+3];
                float s0 = 0, s1 = 0, s2 = 0, s3 = 0;
                #pragma unroll
                for (int ii = 0; ii < 16; ii++) {
                    int i = ib + ii;
                    float4 c = *reinterpret_cast<const float4*>(Cp + (size_t)i * NQ);
                    float u2 = u2s[i];
                    s0 += ex2f(fmaf(c.x, -K2, u2) - M0);
                    s1 += ex2f(fmaf(c.y, -K2, u2) - M1);
                    s2 += ex2f(fmaf(c.z, -K2, u2) - M2);
                    s3 += ex2f(fmaf(c.w, -K2, u2) - M3);
                }
                ssv[rg][cb+0] = s0; ssv[rg][cb+1] = s1;
                ssv[rg][cb+2] = s2; ssv[rg][cb+3] = s3;
                __syncthreads();
                if (tid < 32) {
                    int j = bid * 32 + tid;
                    float S = ssv[0][tid];
                    #pragma unroll
                    for (int q = 1; q < 64; q++) S += ssv[q][tid];
                    float M = smM[tid];
                    g_mv[j] = M;
                    float vold = g_v[j];
                    float vnew = EPSR * (LOG_NU - LN2 * (M + lg2f(S)));
                    g_v[j] = vnew;
                    float dv2 = fabsf(vnew - vold) * K2;
                    #pragma unroll
                    for (int off = 16; off; off >>= 1)
                        dv2 = fmaxf(dv2, __shfl_xor_sync(0xffffffffu, dv2, off));
                    if (tid == 0) atomicMax(&g_dmaxv[par], __float_as_int(dv2));
                }
            }

            if (bid == 0) {
                float e = g_rowerr[tid] + g_rowerr[tid + TPB];
                #pragma unroll
                for (int off = 16; off; off >>= 1)
                    e += __shfl_down_sync(0xffffffffu, e, off);
                if (lane == 0) sered[w] = e;
                __syncthreads();
                if (tid == 0) {
                    float E = 0;
                    #pragma unroll
                    for (int q = 0; q < 16; q++) E += sered[q];
                    if (E < THRESHV) g_done = 1;
                }
            }
        }

        grid_barrier(++bargen);
        done = (*(volatile int*)&g_done) != 0;
    }

    // fused stats epilogue (exact, final v)
    {
        float mx[4] = {-1e30f, -1e30f, -1e30f, -1e30f};
        #pragma unroll
        for (int k = 0; k < 4; k++) {
            int off = tid * 4 + k * 2048;
            float4 vv = *reinterpret_cast<const float4*>(g_v + off);
            #pragma unroll
            for (int r = 0; r < 4; r++) {
                float4 c = *reinterpret_cast<const float4*>(C0 + (size_t)r * NQ + off);
                mx[r] = fmaxf(mx[r], fmaxf(fmaxf(vv.x - c.x, vv.y - c.y),
                                           fmaxf(vv.z - c.z, vv.w - c.w)));
            }
        }
        #pragma unroll
        for (int r = 0; r < 4; r++) {
            float m = mx[r];
            #pragma unroll
            for (int off = 16; off; off >>= 1)
                m = fmaxf(m, __shfl_xor_sync(0xffffffffu, m, off));
            if (lane == 0) mrow[r][w] = m;
        }
        __syncthreads();
        float rm2[4];
        #pragma unroll
        for (int r = 0; r < 4; r++) {
            float mr = mrow[r][0];
            #pragma unroll
            for (int q = 1; q < 16; q++) mr = fmaxf(mr, mrow[r][q]);
            rm2[r] = mr * K2;
        }
        float ss[4] = {0, 0, 0, 0};
        #pragma unroll
        for (int k = 0; k < 4; k++) {
            int off = tid * 4 + k * 2048;
            float4 vv = *reinterpret_cast<const float4*>(g_v + off);
            #pragma unroll
            for (int r = 0; r < 4; r++) {
                float4 c = *reinterpret_cast<const float4*>(C0 + (size_t)r * NQ + off);
                ss[r] += (ex2f(fmaf(vv.x - c.x, K2, -rm2[r])) + ex2f(fmaf(vv.y - c.y, K2, -rm2[r])))
                       + (ex2f(fmaf(vv.z - c.z, K2, -rm2[r])) + ex2f(fmaf(vv.w - c.w, K2, -rm2[r])));
            }
        }
        #pragma unroll
        for (int r = 0; r < 4; r++) {
            float s = ss[r];
            #pragma unroll
            for (int off = 16; off; off >>= 1)
                s += __shfl_xor_sync(0xffffffffu, s, off);
            if (lane == 0) ssum[r][w] = s;
        }
        __syncthreads();
        if (tid < 4) {
            int i = i0 + tid;
            float S = ssum[tid][0];
            #pragma unroll
            for (int q = 1; q < 16; q++) S += ssum[tid][q];
            g_m[i]    = rm2[tid];
            g_sinv[i] = 1.0f / S;
        }
    }
}

// ---------------- out = softmax-weights(C) @ zq via tf32 mma, split-K=16 ----------------
#define BPAD 132
__global__ __launch_bounds__(256) void k_out(const float* __restrict__ B) {
    __shared__ float Ah[128][APAD], Al[128][APAD];
    __shared__ float Bh[16][BPAD], Bl[16][BPAD];
    int tid = threadIdx.x;
    int lane = tid & 31, wid = tid >> 5;
    int warp_m = (wid & 3) * 32, warp_n = (wid >> 2) * 64;
    int m0 = blockIdx.y * 128, n0 = blockIdx.x * 128;
    int kbase = blockIdx.z * (NQ / SPLITK);
    int gid = lane >> 2, tig = lane & 3;

    float acc[2][8][4];
    #pragma unroll
    for (int mi = 0; mi < 2; mi++)
        #pragma unroll
        for (int ni = 0; ni < 8; ni++)
            #pragma unroll
            for (int q = 0; q < 4; q++) acc[mi][ni][q] = 0.0f;

    for (int kk0 = kbase; kk0 < kbase + NQ / SPLITK; kk0 += 16) {
        // A tile: weights (computed inline), 128 x 16
        #pragma unroll
        for (int q = 0; q < 2; q++) {
            int i = tid + q * 256;
            int row = i >> 2, f4 = i & 3;
            int grow = m0 + row;
            float mi2 = g_m[grow], si = g_sinv[grow];
            float4 c  = *reinterpret_cast<const float4*>(g_C + (size_t)grow * NQ + kk0 + f4 * 4);
            float4 vv = *reinterpret_cast<const float4*>(g_v + kk0 + f4 * 4);
            float4 wv;
            wv.x = ex2f(fmaf(vv.x - c.x, K2, -mi2)) * si;
            wv.y = ex2f(fmaf(vv.y - c.y, K2, -mi2)) * si;
            wv.z = ex2f(fmaf(vv.z - c.z, K2, -mi2)) * si;
            wv.w = ex2f(fmaf(vv.w - c.w, K2, -mi2)) * si;
            float4 hx, lx;
            hx.x = __uint_as_float(tf32r(wv.x)); lx.x = __uint_as_float(tf32r(wv.x - hx.x));
            hx.y = __uint_as_float(tf32r(wv.y)); lx.y = __uint_as_float(tf32r(wv.y - hx.y));
            hx.z = __uint_as_float(tf32r(wv.z)); lx.z = __uint_as_float(tf32r(wv.z - hx.z));
            hx.w = __uint_as_float(tf32r(wv.w)); lx.w = __uint_as_float(tf32r(wv.w - hx.w));
            *reinterpret_cast<float4*>(&Ah[row][f4 * 4]) = hx;
            *reinterpret_cast<float4*>(&Al[row][f4 * 4]) = lx;
        }
        // B tile: zq[k][n], 16 x 128
        #pragma unroll
        for (int q = 0; q < 2; q++) {
            int i = tid + q * 256;
            int krow = i >> 5, f4c = i & 31;
            float4 b = *reinterpret_cast<const float4*>(B + (size_t)(kk0 + krow) * DD + n0 + f4c * 4);
            float4 hx, lx;
            hx.x = __uint_as_float(tf32r(b.x)); lx.x = __uint_as_float(tf32r(b.x - hx.x));
            hx.y = __uint_as_float(tf32r(b.y)); lx.y = __uint_as_float(tf32r(b.y - hx.y));
            hx.z = __uint_as_float(tf32r(b.z)); lx.z = __uint_as_float(tf32r(b.z - hx.z));
            hx.w = __uint_as_float(tf32r(b.w)); lx.w = __uint_as_float(tf32r(b.w - hx.w));
            *reinterpret_cast<float4*>(&Bh[krow][f4c * 4]) = hx;
            *reinterpret_cast<float4*>(&Bl[krow][f4c * 4]) = lx;
        }
        __syncthreads();
        #pragma unroll
        for (int k8 = 0; k8 < 2; k8++) {
            int kc = k8 * 8 + tig;
            uint32_t ah[2][4], al[2][4];
            #pragma unroll
            for (int mi = 0; mi < 2; mi++) {
                int rb = warp_m + mi * 16 + gid;
                ah[mi][0] = __float_as_uint(Ah[rb][kc]);
                ah[mi][1] = __float_as_uint(Ah[rb + 8][kc]);
                ah[mi][2] = __float_as_uint(Ah[rb][kc + 4]);
                ah[mi][3] = __float_as_uint(Ah[rb + 8][kc + 4]);
                al[mi][0] = __float_as_uint(Al[rb][kc]);
                al[mi][1] = __float_as_uint(Al[rb + 8][kc]);
                al[mi][2] = __float_as_uint(Al[rb][kc + 4]);
                al[mi][3] = __float_as_uint(Al[rb + 8][kc + 4]);
            }
            #pragma unroll
            for (int ni = 0; ni < 8; ni++) {
                int nb = warp_n + ni * 8 + gid;
                uint32_t bh0 = __float_as_uint(Bh[k8 * 8 + tig][nb]);
                uint32_t bh1 = __float_as_uint(Bh[k8 * 8 + tig + 4][nb]);
                uint32_t bl0 = __float_as_uint(Bl[k8 * 8 + tig][nb]);
                uint32_t bl1 = __float_as_uint(Bl[k8 * 8 + tig + 4][nb]);
                #pragma unroll
                for (int mi = 0; mi < 2; mi++) {
                    mma_tf32(acc[mi][ni], ah[mi][0], ah[mi][1], ah[mi][2], ah[mi][3], bh0, bh1);
                    mma_tf32(acc[mi][ni], ah[mi][0], ah[mi][1], ah[mi][2], ah[mi][3], bl0, bl1);
                    mma_tf32(acc[mi][ni], al[mi][0], al[mi][1], al[mi][2], al[mi][3], bh0, bh1);
                }
            }
        }
        __syncthreads();
    }
    float* P = g_part + (size_t)blockIdx.z * NS * DD;
    #pragma unroll
    for (int mi = 0; mi < 2; mi++) {
        int r0 = m0 + warp_m + mi * 16 + gid;
        #pragma unroll
        for (int ni = 0; ni < 8; ni++) {
            int c0 = n0 + warp_n + ni * 8 + 2 * tig;
            float2 w0 = { acc[mi][ni][0], acc[mi][ni][1] };
            float2 w1 = { acc[mi][ni][2], acc[mi][ni][3] };
            *reinterpret_cast<float2*>(P + (size_t)r0 * DD + c0) = w0;
            *reinterpret_cast<float2*>(P + (size_t)(r0 + 8) * DD + c0) = w1;
        }
    }
}

// ---------------- reduce split-K partials ----------------
__global__ void k_reduce(float* __restrict__ out) {
    int t = blockIdx.x * blockDim.x + threadIdx.x;
    float s = 0.0f;
    #pragma unroll
    for (int q = 0; q < SPLITK; q++) s += g_part[(size_t)q * NS * DD + t];
    out[t] = s;
}

// ---------------- copy z_query ----------------
__global__ void k_copy(const float* __restrict__ zq, float* __restrict__ out) {
    int t = blockIdx.x * blockDim.x + threadIdx.x;
    reinterpret_cast<float4*>(out)[t] = reinterpret_cast<const float4*>(zq)[t];
}

// ---------------- launch ----------------
extern "C" void kernel_launch(void* const* d_in, const int* in_sizes, int n_in,
                              void* d_out, int out_size) {
    const float* zs = (const float*)d_in[0];
    const float* zq = (const float*)d_in[1];
    if (n_in >= 2 && in_sizes[0] == NQ * DD) {
        const float* t = zs; zs = zq; zq = t;
    }
    float* out = (float*)d_out;

    k_init<<<(NQ + 255) / 256, 256>>>();
    k_norms<<<(NS + NQ) / 8, 256>>>(zs, zq);
    k_cost<<<dim3(NQ / 128, NS / 128), 256>>>(zs, zq);
    k_sink<<<GRIDB, TPB>>>();
    k_out<<<dim3(DD / 128, NS / 128, SPLITK), 256>>>(zq);
    k_reduce<<<(NS * DD) / 256, 256>>>(out);
    k_copy<<<(NQ * DD / 4) / 256, 256>>>(zq, out + NS * DD);
}